// round 10
// baseline (speedup 1.0000x reference)
#include <cuda_runtime.h>
#include <math.h>
#include <stdint.h>

#define BB   2
#define TT   2048
#define DD   2048
#define NH   16
#define NKV  4
#define HDIM 128

// Scratch (allocation-free rule: __device__ globals)
__device__ float g_q[BB*TT*NH*HDIM];    // [B*T, 2048] (tf32+scale after rope)
__device__ float g_k[BB*TT*NKV*HDIM];   // [B*T, 512]  (tf32 after rope)
__device__ float g_v[BB*TT*NKV*HDIM];   // [B*T, 512]  (tf32 after rope pass)
__device__ float g_o[BB*TT*NH*HDIM];    // [B*T, 2048] (tf32-rounded by attn)
// tf32-preconverted operands
__device__ float g_xt [BB*TT*DD];
__device__ float g_wqt[DD*NH*HDIM];
__device__ float g_wkt[DD*NKV*HDIM];
__device__ float g_wvt[DD*NKV*HDIM];
__device__ float g_wot[DD*DD];

__device__ __forceinline__ uint32_t f32_to_tf32(float x) {
    uint32_t r;
    asm("cvt.rna.tf32.f32 %0, %1;" : "=r"(r) : "f"(x));
    return r;
}

__device__ __forceinline__ void mma_tf32(float c[4],
                                         uint32_t a0, uint32_t a1, uint32_t a2, uint32_t a3,
                                         uint32_t b0, uint32_t b1) {
    asm volatile(
        "mma.sync.aligned.m16n8k8.row.col.f32.tf32.tf32.f32 "
        "{%0,%1,%2,%3}, {%4,%5,%6,%7}, {%8,%9}, {%0,%1,%2,%3};\n"
        : "+f"(c[0]), "+f"(c[1]), "+f"(c[2]), "+f"(c[3])
        : "r"(a0), "r"(a1), "r"(a2), "r"(a3), "r"(b0), "r"(b1));
}

__device__ __forceinline__ void cp_async16(uint32_t smem_addr, const void* gptr) {
    asm volatile("cp.async.cg.shared.global [%0], [%1], 16;\n"
                 :: "r"(smem_addr), "l"(gptr));
}
__device__ __forceinline__ void cp_async4(uint32_t smem_addr, const void* gptr) {
    asm volatile("cp.async.ca.shared.global [%0], [%1], 4;\n"
                 :: "r"(smem_addr), "l"(gptr));
}
__device__ __forceinline__ void cp_commit() {
    asm volatile("cp.async.commit_group;\n" ::: "memory");
}
template <int N>
__device__ __forceinline__ void cp_wait() {
    asm volatile("cp.async.wait_group %0;\n" :: "n"(N) : "memory");
}

// ---------------------------------------------------------------------------
// Fused tf32 pre-conversion of x + all weights (single launch)
// ---------------------------------------------------------------------------
#define CVT_N4 4718592
__global__ __launch_bounds__(256)
void cvt_all_kernel(const float4* __restrict__ x,  const float4* __restrict__ wq,
                    const float4* __restrict__ wk, const float4* __restrict__ wv,
                    const float4* __restrict__ wo,
                    float4* __restrict__ xt,  float4* __restrict__ wqt,
                    float4* __restrict__ wkt, float4* __restrict__ wvt,
                    float4* __restrict__ wot) {
    int i = blockIdx.x * blockDim.x + threadIdx.x;
    const float4* s; float4* d; int off;
    if      (i < 2097152) { s = x;  d = xt;  off = 0; }
    else if (i < 3145728) { s = wq; d = wqt; off = 2097152; }
    else if (i < 3407872) { s = wk; d = wkt; off = 3145728; }
    else if (i < 3670016) { s = wv; d = wvt; off = 3407872; }
    else if (i < CVT_N4)  { s = wo; d = wot; off = 3670016; }
    else return;
    int j = i - off;
    float4 f = s[j];
    float4 o;
    o.x = __uint_as_float(f32_to_tf32(f.x));
    o.y = __uint_as_float(f32_to_tf32(f.y));
    o.z = __uint_as_float(f32_to_tf32(f.z));
    o.w = __uint_as_float(f32_to_tf32(f.w));
    d[j] = o;
}

// ---------------------------------------------------------------------------
// TF32 mma.sync GEMM: 256 threads (8 warps), warp tile 64x32.
// BM=128, BN=128, BK=32, 3-stage cp.async, ONE sync per iteration.
// ---------------------------------------------------------------------------
#define APITCH 36
#define BPITCH 136
#define ASZ    (128 * APITCH)
#define BSZ    (32 * BPITCH)
#define STG    (ASZ + BSZ)
#define NSTG   3
#define GEMM_SMEM_BYTES (NSTG * STG * 4)

__device__ __forceinline__ void gemm_fill(const float* __restrict__ A,
                                          const float* __restrict__ B,
                                          int K, int N, int k0,
                                          uint32_t aAddr, uint32_t bAddr,
                                          int a_row, int a_c4, int b_kr, int b_c4) {
    const float* srcA = A + (size_t)a_row * K + k0 + a_c4;
    uint32_t dstA = aAddr + (a_row * APITCH + a_c4) * 4;
    #pragma unroll
    for (int v = 0; v < 4; v++)
        cp_async16(dstA + v * 16, srcA + v * 4);
    #pragma unroll
    for (int v = 0; v < 4; v++) {
        int kr = b_kr + v * 8;
        cp_async16(bAddr + (kr * BPITCH + b_c4) * 4,
                   B + (size_t)(k0 + kr) * N + b_c4);
    }
}

__device__ __forceinline__ void gemm_body(
    const float* __restrict__ A, const float* __restrict__ B,
    float* __restrict__ C, int N, int K, uint32_t smem_base)
{
    const int tid  = threadIdx.x;
    const int wid  = tid >> 5;
    const int lane = tid & 31;
    const int g    = lane >> 2;
    const int tig  = lane & 3;

    const int warp_m = (wid & 1) * 64;
    const int warp_n = (wid >> 1) * 32;

    uint32_t* sm = (uint32_t*)__cvta_shared_to_generic(smem_base);

    const int a_row = tid >> 1;
    const int a_c4  = (tid & 1) << 4;
    const int b_kr  = tid >> 5;
    const int b_c4  = lane << 2;

    float acc[4][4][4];
    #pragma unroll
    for (int i = 0; i < 4; i++)
        #pragma unroll
        for (int j = 0; j < 4; j++)
            #pragma unroll
            for (int c = 0; c < 4; c++) acc[i][j][c] = 0.0f;

    const int niter = K >> 5;

    #pragma unroll
    for (int p = 0; p < NSTG - 1; p++) {
        uint32_t ab = smem_base + (p * STG) * 4;
        gemm_fill(A, B, K, N, p << 5, ab, ab + ASZ * 4, a_row, a_c4, b_kr, b_c4);
        cp_commit();
    }

    for (int i = 0; i < niter; i++) {
        cp_wait<NSTG - 2>();
        __syncthreads();

        const int ft = i + NSTG - 1;
        if (ft < niter) {
            const int fs = ft % NSTG;
            uint32_t ab = smem_base + (fs * STG) * 4;
            gemm_fill(A, B, K, N, ft << 5, ab, ab + ASZ * 4, a_row, a_c4, b_kr, b_c4);
        }
        cp_commit();

        const int cur = i % NSTG;
        const uint32_t* As = sm + cur * STG;
        const uint32_t* Bs = As + ASZ;

        #pragma unroll
        for (int ks = 0; ks < 4; ks++) {
            const int kk = ks * 8;
            uint32_t af[4][4];
            #pragma unroll
            for (int mt = 0; mt < 4; mt++) {
                int ar = warp_m + mt * 16 + g;
                af[mt][0] = As[ar * APITCH + kk + tig];
                af[mt][1] = As[(ar + 8) * APITCH + kk + tig];
                af[mt][2] = As[ar * APITCH + kk + tig + 4];
                af[mt][3] = As[(ar + 8) * APITCH + kk + tig + 4];
            }
            uint32_t bf[4][2];
            #pragma unroll
            for (int nt = 0; nt < 4; nt++) {
                int bc = warp_n + nt * 8 + g;
                bf[nt][0] = Bs[(kk + tig) * BPITCH + bc];
                bf[nt][1] = Bs[(kk + tig + 4) * BPITCH + bc];
            }
            #pragma unroll
            for (int mt = 0; mt < 4; mt++)
                #pragma unroll
                for (int nt = 0; nt < 4; nt++)
                    mma_tf32(acc[mt][nt], af[mt][0], af[mt][1], af[mt][2], af[mt][3],
                             bf[nt][0], bf[nt][1]);
        }
    }

    float* Cw = C + (size_t)warp_m * N + warp_n;
    #pragma unroll
    for (int mt = 0; mt < 4; mt++) {
        #pragma unroll
        for (int nt = 0; nt < 4; nt++) {
            int row = mt * 16 + g;
            int col = nt * 8 + 2 * tig;
            *(float2*)(Cw + (size_t)row * N + col) =
                make_float2(acc[mt][nt][0], acc[mt][nt][1]);
            *(float2*)(Cw + (size_t)(row + 8) * N + col) =
                make_float2(acc[mt][nt][2], acc[mt][nt][3]);
        }
    }
}

__global__ __launch_bounds__(256, 2)
void qkv_gemm_kernel(float* __restrict__ gq, float* __restrict__ gk,
                     float* __restrict__ gv) {
    extern __shared__ uint32_t smraw[];
    uint32_t smem_base = (uint32_t)__cvta_generic_to_shared(smraw);

    const int bx = blockIdx.x;
    const int by = blockIdx.y;

    const float* Bsel;
    float* Csel;
    int Nsel, colb;
    if (bx < 16)      { Bsel = g_wqt; Csel = gq; Nsel = 2048; colb = bx * 128; }
    else if (bx < 20) { Bsel = g_wkt; Csel = gk; Nsel = 512;  colb = (bx - 16) * 128; }
    else              { Bsel = g_wvt; Csel = gv; Nsel = 512;  colb = (bx - 20) * 128; }

    gemm_body(g_xt + (size_t)by * 128 * DD, Bsel + colb,
              Csel + (size_t)by * 128 * Nsel + colb, Nsel, DD, smem_base);
}

__global__ __launch_bounds__(256, 2)
void wo_gemm_kernel(float* __restrict__ C) {
    extern __shared__ uint32_t smraw[];
    uint32_t smem_base = (uint32_t)__cvta_generic_to_shared(smraw);
    gemm_body(g_o + (size_t)blockIdx.y * 128 * DD,
              g_wot + blockIdx.x * 128,
              C + (size_t)blockIdx.y * 128 * DD + blockIdx.x * 128,
              DD, DD, smem_base);
}

// ---------------------------------------------------------------------------
// RoPE in-place on g_q (scale+tf32 folded), g_k (tf32 folded), g_v (tf32 pass)
// ---------------------------------------------------------------------------
#define LOG2_THETA_OVER_HALF 0.20762050593046128f   // log2(10000)/64
#define ROPE_TOTQ (BB*TT*NH*64)
#define ROPE_TOTK (BB*TT*NKV*64)
#define ROPE_TOTV (BB*TT*NKV*HDIM)
#define ROPE_TOT  (ROPE_TOTQ + ROPE_TOTK + ROPE_TOTV)

__global__ __launch_bounds__(256)
void rope_kernel() {
    const float scale = 0.08838834764831845f;  // 1/sqrt(128)
    int idx = blockIdx.x * blockDim.x + threadIdx.x;
    if (idx < ROPE_TOTQ) {
        int d  = idx & 63;
        int h  = (idx >> 6) % NH;
        int bt = idx / (64 * NH);
        int t  = bt & (TT - 1);
        float inv = exp2f(-(float)d * LOG2_THETA_OVER_HALF);
        float ang = (float)t * inv;
        float s, c;
        sincosf(ang, &s, &c);
        float* p = g_q + (size_t)bt * (NH * HDIM) + h * HDIM;
        float x1 = p[d], x2 = p[d + 64];
        p[d]      = __uint_as_float(f32_to_tf32((x1 * c - x2 * s) * scale));
        p[d + 64] = __uint_as_float(f32_to_tf32((x2 * c + x1 * s) * scale));
    } else if (idx < ROPE_TOTQ + ROPE_TOTK) {
        int j  = idx - ROPE_TOTQ;
        int d  = j & 63;
        int h  = (j >> 6) % NKV;
        int bt = j / (64 * NKV);
        int t  = bt & (TT - 1);
        float inv = exp2f(-(float)d * LOG2_THETA_OVER_HALF);
        float ang = (float)t * inv;
        float s, c;
        sincosf(ang, &s, &c);
        float* p = g_k + (size_t)bt * (NKV * HDIM) + h * HDIM;
        float x1 = p[d], x2 = p[d + 64];
        p[d]      = __uint_as_float(f32_to_tf32(x1 * c - x2 * s));
        p[d + 64] = __uint_as_float(f32_to_tf32(x2 * c + x1 * s));
    } else if (idx < ROPE_TOT) {
        int j = idx - ROPE_TOTQ - ROPE_TOTK;
        g_v[j] = __uint_as_float(f32_to_tf32(g_v[j]));
    }
}

// ---------------------------------------------------------------------------
// Tensor-core flash attention (tf32 mma.sync), BM=128, BN=64, HD=128.
// 512 threads = 16 warps: rg = wid&7 owns 16 rows; wn = wid>>3 splits
// keys (S phase) and HD (PV phase). Cross-half softmax via redM/redS.
// smem words:
//   Qs[128][136]=17408 | Ks[64][136]=8704 | Vs[2][64][136]=17408 |
//   Ps[128][72]=9216 | redM[2][128]=256 | redS[2][128]=256 | mask[2][64]=128
//   total 53376 words = 213504 B
// ---------------------------------------------------------------------------
#define KP 136
#define PP 72
#define QS_OFF   0
#define KS_OFF   17408
#define VS_OFF   26112
#define PS_OFF   43520
#define RM_OFF   52736
#define RS_OFF   52992
#define MASK_OFF 53248
#define ATTN_SMEM_BYTES (53376 * 4)
#define ATTN_THREADS 512

__global__ __launch_bounds__(ATTN_THREADS, 1)
void attn_mma_kernel(const int* __restrict__ mask, const int* __restrict__ causal_p) {
    extern __shared__ uint32_t sm[];
    const uint32_t smem_base = (uint32_t)__cvta_generic_to_shared(sm);
    uint32_t* Qs    = sm + QS_OFF;
    uint32_t* Ks    = sm + KS_OFF;
    uint32_t* Ps    = sm + PS_OFF;
    float*    redM  = (float*)(sm + RM_OFF);
    float*    redS  = (float*)(sm + RS_OFF);
    int*      maskS = (int*)(sm + MASK_OFF);

    const int tid  = threadIdx.x;
    const int wid  = tid >> 5;
    const int lane = tid & 31;
    const int g    = lane >> 2;
    const int tig  = lane & 3;
    const int rg   = wid & 7;     // row group (16 rows)
    const int wn   = wid >> 3;    // half index (keys for S, HD for PV)

    const int qb  = (gridDim.x - 1) - blockIdx.x;   // LPT: long CTAs first
    const int h   = blockIdx.y;
    const int b   = blockIdx.z;
    const int kvh = h >> 2;
    const int causal = causal_p[0];

    const float* qbase = g_q + ((size_t)b * TT + qb * 128) * 2048 + h * HDIM;
    const float* kbase = g_k + (size_t)b * TT * 512 + kvh * HDIM;
    const float* vbase = g_v + (size_t)b * TT * 512 + kvh * HDIM;
    const int*   mbase = mask + b * TT;

    // ---- prologue: async fill Q (whole), K0, V0 buf0, mask0 ----
    #pragma unroll
    for (int it = 0; it < 8; it++) {
        int task = tid + ATTN_THREADS * it;
        int r = task >> 5;
        int c = (task & 31) << 2;
        cp_async16(smem_base + (QS_OFF + r * KP + c) * 4,
                   qbase + (size_t)r * 2048 + c);
    }
    #pragma unroll
    for (int it = 0; it < 4; it++) {
        int task = tid + ATTN_THREADS * it;
        int r = task >> 5;
        int c = (task & 31) << 2;
        cp_async16(smem_base + (KS_OFF + r * KP + c) * 4,
                   kbase + (size_t)r * 512 + c);
        cp_async16(smem_base + (VS_OFF + r * KP + c) * 4,
                   vbase + (size_t)r * 512 + c);
    }
    if (tid < 64)
        cp_async4(smem_base + (MASK_OFF + tid) * 4, mbase + tid);
    cp_commit();

    const int r0  = 16 * rg + g;
    const int r1  = r0 + 8;
    const int qg0 = qb * 128 + r0;
    const int qg1 = qb * 128 + r1;

    float accO[8][4];   // 16 rows x 64 HD cols (half wn)
    #pragma unroll
    for (int nt = 0; nt < 8; nt++)
        #pragma unroll
        for (int c = 0; c < 4; c++) accO[nt][c] = 0.0f;

    float m0 = -1e30f, m1 = -1e30f, l0 = 0.0f, l1 = 0.0f;

    const int kbmax = causal ? (2 * qb + 1) : (TT / 64 - 1);

    for (int kb = 0; kb <= kbmax; kb++) {
        const int kr0 = kb * 64;
        const int cbuf = kb & 1;

        cp_wait<0>();
        __syncthreads();            // tiles ready; prior PV done

        // ---- S = Q @ K^T : warp computes 16 x 32 (keys 32*wn..) ----
        float sacc[4][4];
        #pragma unroll
        for (int nt = 0; nt < 4; nt++)
            #pragma unroll
            for (int c = 0; c < 4; c++) sacc[nt][c] = 0.0f;

        #pragma unroll
        for (int ks = 0; ks < 16; ks++) {
            const uint32_t* qr = &Qs[r0 * KP + ks * 8 + tig];
            uint32_t a0 = qr[0];
            uint32_t a2 = qr[4];
            uint32_t a1 = qr[8 * KP];
            uint32_t a3 = qr[8 * KP + 4];
            #pragma unroll
            for (int nt = 0; nt < 4; nt++) {
                const uint32_t* kr = &Ks[(32 * wn + 8 * nt + g) * KP + ks * 8 + tig];
                mma_tf32(sacc[nt], a0, a1, a2, a3, kr[0], kr[4]);
            }
        }

        // ---- mask + half-local row max, publish to redM ----
        const int* mcur = maskS + cbuf * 64;
        float lm0 = -1e30f, lm1 = -1e30f;
        #pragma unroll
        for (int nt = 0; nt < 4; nt++) {
            #pragma unroll
            for (int e = 0; e < 2; e++) {
                int c  = 32 * wn + 8 * nt + 2 * tig + e;
                int kg = kr0 + c;
                bool mz = (mcur[c] == 0);
                if (mz || (causal && kg > qg0)) sacc[nt][e]     = -1e30f;
                if (mz || (causal && kg > qg1)) sacc[nt][e + 2] = -1e30f;
                lm0 = fmaxf(lm0, sacc[nt][e]);
                lm1 = fmaxf(lm1, sacc[nt][e + 2]);
            }
        }
        lm0 = fmaxf(lm0, __shfl_xor_sync(0xffffffffu, lm0, 1));
        lm0 = fmaxf(lm0, __shfl_xor_sync(0xffffffffu, lm0, 2));
        lm1 = fmaxf(lm1, __shfl_xor_sync(0xffffffffu, lm1, 1));
        lm1 = fmaxf(lm1, __shfl_xor_sync(0xffffffffu, lm1, 2));
        if (tig == 0) {
            redM[wn * 128 + r0] = lm0;
            redM[wn * 128 + r1] = lm1;
        }
        __syncthreads();            // redM visible; Ks free for prefetch

        // ---- prefetch K[kb+1], V[kb+1] (alt buf), mask[kb+1] ----
        if (kb < kbmax) {
            const int nr0 = kr0 + 64;
            const int nbuf = (kb + 1) & 1;
            #pragma unroll
            for (int it = 0; it < 4; it++) {
                int task = tid + ATTN_THREADS * it;
                int r = task >> 5;
                int c = (task & 31) << 2;
                cp_async16(smem_base + (KS_OFF + r * KP + c) * 4,
                           kbase + (size_t)(nr0 + r) * 512 + c);
                cp_async16(smem_base + (VS_OFF + nbuf * 8704 + r * KP + c) * 4,
                           vbase + (size_t)(nr0 + r) * 512 + c);
            }
            if (tid < 64)
                cp_async4(smem_base + (MASK_OFF + nbuf * 64 + tid) * 4,
                          mbase + nr0 + tid);
        }
        cp_commit();

        // ---- combine maxima, exp over own half, publish sums + P ----
        float mn0 = fmaxf(m0, fmaxf(redM[r0], redM[128 + r0]));
        float mn1 = fmaxf(m1, fmaxf(redM[r1], redM[128 + r1]));
        float esc0 = __expf(m0 - mn0);
        float esc1 = __expf(m1 - mn1);

        float ls0 = 0.0f, ls1 = 0.0f;
        #pragma unroll
        for (int nt = 0; nt < 4; nt++) {
            float p0 = __expf(sacc[nt][0] - mn0);
            float p1 = __expf(sacc[nt][1] - mn0);
            float p2 = __expf(sacc[nt][2] - mn1);
            float p3 = __expf(sacc[nt][3] - mn1);
            ls0 += p0 + p1;
            ls1 += p2 + p3;
            int c = 32 * wn + 8 * nt + 2 * tig;
            uint32_t* d0 = &Ps[r0 * PP + c];
            uint32_t* d1 = &Ps[r1 * PP + c];
            d0[0] = f32_to_tf32(p0);
            d0[1] = f32_to_tf32(p1);
            d1[0] = f32_to_tf32(p2);
            d1[1] = f32_to_tf32(p3);
        }
        ls0 += __shfl_xor_sync(0xffffffffu, ls0, 1);
        ls0 += __shfl_xor_sync(0xffffffffu, ls0, 2);
        ls1 += __shfl_xor_sync(0xffffffffu, ls1, 1);
        ls1 += __shfl_xor_sync(0xffffffffu, ls1, 2);
        if (tig == 0) {
            redS[wn * 128 + r0] = ls0;
            redS[wn * 128 + r1] = ls1;
        }

        // rescale accumulators while waiting
        #pragma unroll
        for (int nt = 0; nt < 8; nt++) {
            accO[nt][0] *= esc0; accO[nt][1] *= esc0;
            accO[nt][2] *= esc1; accO[nt][3] *= esc1;
        }
        __syncthreads();            // Ps + redS visible

        l0 = l0 * esc0 + redS[r0] + redS[128 + r0];
        l1 = l1 * esc1 + redS[r1] + redS[128 + r1];
        m0 = mn0;
        m1 = mn1;

        // ---- O += P @ V : warp computes 16 rows x 64 HD (half wn) ----
        const uint32_t* Vc = sm + VS_OFF + cbuf * 8704;
        #pragma unroll
        for (int ks = 0; ks < 8; ks++) {
            const uint32_t* pr = &Ps[r0 * PP + ks * 8 + tig];
            uint32_t a0 = pr[0];
            uint32_t a2 = pr[4];
            uint32_t a1 = pr[8 * PP];
            uint32_t a3 = pr[8 * PP + 4];
            #pragma unroll
            for (int nt = 0; nt < 8; nt++) {
                const uint32_t* vr = &Vc[(ks * 8 + tig) * KP + 64 * wn + 8 * nt + g];
                mma_tf32(accO[nt], a0, a1, a2, a3, vr[0], vr[4 * KP]);
            }
        }
    }

    float invl0 = 1.0f / l0;
    float invl1 = 1.0f / l1;
    float* ob0 = g_o + ((size_t)b * TT + qb * 128 + r0) * 2048 + h * HDIM
                 + 64 * wn + 2 * tig;
    float* ob1 = g_o + ((size_t)b * TT + qb * 128 + r1) * 2048 + h * HDIM
                 + 64 * wn + 2 * tig;
    #pragma unroll
    for (int nt = 0; nt < 8; nt++) {
        *(float2*)(ob0 + 8 * nt) = make_float2(
            __uint_as_float(f32_to_tf32(accO[nt][0] * invl0)),
            __uint_as_float(f32_to_tf32(accO[nt][1] * invl0)));
        *(float2*)(ob1 + 8 * nt) = make_float2(
            __uint_as_float(f32_to_tf32(accO[nt][2] * invl1)),
            __uint_as_float(f32_to_tf32(accO[nt][3] * invl1)));
    }
}

// ---------------------------------------------------------------------------
extern "C" void kernel_launch(void* const* d_in, const int* in_sizes, int n_in,
                              void* d_out, int out_size) {
    const float* x      = (const float*)d_in[0];
    const int*   mask   = (const int*)d_in[1];
    const int*   causal = (const int*)d_in[2];
    const float* wq     = (const float*)d_in[3];
    const float* wk     = (const float*)d_in[4];
    const float* wv     = (const float*)d_in[5];
    const float* wo     = (const float*)d_in[6];
    float* out = (float*)d_out;

    float *gq, *gk, *gv, *xt, *wqt, *wkt, *wvt, *wot;
    cudaGetSymbolAddress((void**)&gq,  g_q);
    cudaGetSymbolAddress((void**)&gk,  g_k);
    cudaGetSymbolAddress((void**)&gv,  g_v);
    cudaGetSymbolAddress((void**)&xt,  g_xt);
    cudaGetSymbolAddress((void**)&wqt, g_wqt);
    cudaGetSymbolAddress((void**)&wkt, g_wkt);
    cudaGetSymbolAddress((void**)&wvt, g_wvt);
    cudaGetSymbolAddress((void**)&wot, g_wot);

    const int M = BB * TT;  // 4096

    cudaFuncSetAttribute(qkv_gemm_kernel, cudaFuncAttributeMaxDynamicSharedMemorySize,
                         GEMM_SMEM_BYTES);
    cudaFuncSetAttribute(wo_gemm_kernel, cudaFuncAttributeMaxDynamicSharedMemorySize,
                         GEMM_SMEM_BYTES);
    cudaFuncSetAttribute(attn_mma_kernel, cudaFuncAttributeMaxDynamicSharedMemorySize,
                         ATTN_SMEM_BYTES);

    // Pre-convert operands to tf32 (single fused launch)
    cvt_all_kernel<<<(CVT_N4 + 255) / 256, 256>>>(
        (const float4*)x,  (const float4*)wq, (const float4*)wk,
        (const float4*)wv, (const float4*)wo,
        (float4*)xt, (float4*)wqt, (float4*)wkt, (float4*)wvt, (float4*)wot);

    // Fused QKV projection
    qkv_gemm_kernel<<<dim3(24, M / 128), 256, GEMM_SMEM_BYTES>>>(gq, gk, gv);

    // RoPE (+ tf32 rounding of q (scaled), k, v)
    rope_kernel<<<(ROPE_TOT + 255) / 256, 256>>>();

    // Attention (mma.sync tensor cores), BM=128, 16 warps, async pipelined
    attn_mma_kernel<<<dim3(TT / 128, NH, BB), ATTN_THREADS, ATTN_SMEM_BYTES>>>(mask, causal);

    // Output projection
    wo_gemm_kernel<<<dim3(DD / 128, M / 128), 256, GEMM_SMEM_BYTES>>>(out);
}

// round 11
// speedup vs baseline: 1.1015x; 1.1015x over previous
#include <cuda_runtime.h>
#include <math.h>
#include <stdint.h>

#define BB   2
#define TT   2048
#define DD   2048
#define NH   16
#define NKV  4
#define HDIM 128

// Scratch (allocation-free rule: __device__ globals)
__device__ float g_q[BB*TT*NH*HDIM];    // [B*T, 2048] (tf32+scale after rope)
__device__ float g_k[BB*TT*NKV*HDIM];   // [B*T, 512]  (tf32 after rope)
__device__ float g_v[BB*TT*NKV*HDIM];   // [B*T, 512]  (tf32 after rope pass)
__device__ float g_o[BB*TT*NH*HDIM];    // [B*T, 2048] (tf32-rounded by attn)
// tf32-preconverted operands
__device__ float g_xt [BB*TT*DD];
__device__ float g_wqt[DD*NH*HDIM];
__device__ float g_wkt[DD*NKV*HDIM];
__device__ float g_wvt[DD*NKV*HDIM];
__device__ float g_wot[DD*DD];

__device__ __forceinline__ uint32_t f32_to_tf32(float x) {
    uint32_t r;
    asm("cvt.rna.tf32.f32 %0, %1;" : "=r"(r) : "f"(x));
    return r;
}

__device__ __forceinline__ void mma_tf32(float c[4],
                                         uint32_t a0, uint32_t a1, uint32_t a2, uint32_t a3,
                                         uint32_t b0, uint32_t b1) {
    asm volatile(
        "mma.sync.aligned.m16n8k8.row.col.f32.tf32.tf32.f32 "
        "{%0,%1,%2,%3}, {%4,%5,%6,%7}, {%8,%9}, {%0,%1,%2,%3};\n"
        : "+f"(c[0]), "+f"(c[1]), "+f"(c[2]), "+f"(c[3])
        : "r"(a0), "r"(a1), "r"(a2), "r"(a3), "r"(b0), "r"(b1));
}

__device__ __forceinline__ void cp_async16(uint32_t smem_addr, const void* gptr) {
    asm volatile("cp.async.cg.shared.global [%0], [%1], 16;\n"
                 :: "r"(smem_addr), "l"(gptr));
}
__device__ __forceinline__ void cp_async4(uint32_t smem_addr, const void* gptr) {
    asm volatile("cp.async.ca.shared.global [%0], [%1], 4;\n"
                 :: "r"(smem_addr), "l"(gptr));
}
__device__ __forceinline__ void cp_commit() {
    asm volatile("cp.async.commit_group;\n" ::: "memory");
}
template <int N>
__device__ __forceinline__ void cp_wait() {
    asm volatile("cp.async.wait_group %0;\n" :: "n"(N) : "memory");
}

// ---------------------------------------------------------------------------
// Fused tf32 pre-conversion of x + all weights (single launch)
// ---------------------------------------------------------------------------
#define CVT_N4 4718592
__global__ __launch_bounds__(256)
void cvt_all_kernel(const float4* __restrict__ x,  const float4* __restrict__ wq,
                    const float4* __restrict__ wk, const float4* __restrict__ wv,
                    const float4* __restrict__ wo,
                    float4* __restrict__ xt,  float4* __restrict__ wqt,
                    float4* __restrict__ wkt, float4* __restrict__ wvt,
                    float4* __restrict__ wot) {
    int i = blockIdx.x * blockDim.x + threadIdx.x;
    const float4* s; float4* d; int off;
    if      (i < 2097152) { s = x;  d = xt;  off = 0; }
    else if (i < 3145728) { s = wq; d = wqt; off = 2097152; }
    else if (i < 3407872) { s = wk; d = wkt; off = 3145728; }
    else if (i < 3670016) { s = wv; d = wvt; off = 3407872; }
    else if (i < CVT_N4)  { s = wo; d = wot; off = 3670016; }
    else return;
    int j = i - off;
    float4 f = s[j];
    float4 o;
    o.x = __uint_as_float(f32_to_tf32(f.x));
    o.y = __uint_as_float(f32_to_tf32(f.y));
    o.z = __uint_as_float(f32_to_tf32(f.z));
    o.w = __uint_as_float(f32_to_tf32(f.w));
    d[j] = o;
}

// ---------------------------------------------------------------------------
// TF32 mma.sync GEMM: 256 threads (8 warps), warp tile 64x32.
// BM=128, BN=128, BK=32, 3-stage cp.async, ONE sync per iteration.
// ---------------------------------------------------------------------------
#define APITCH 36
#define BPITCH 136
#define ASZ    (128 * APITCH)
#define BSZ    (32 * BPITCH)
#define STG    (ASZ + BSZ)
#define NSTG   3
#define GEMM_SMEM_BYTES (NSTG * STG * 4)

__device__ __forceinline__ void gemm_fill(const float* __restrict__ A,
                                          const float* __restrict__ B,
                                          int K, int N, int k0,
                                          uint32_t aAddr, uint32_t bAddr,
                                          int a_row, int a_c4, int b_kr, int b_c4) {
    const float* srcA = A + (size_t)a_row * K + k0 + a_c4;
    uint32_t dstA = aAddr + (a_row * APITCH + a_c4) * 4;
    #pragma unroll
    for (int v = 0; v < 4; v++)
        cp_async16(dstA + v * 16, srcA + v * 4);
    #pragma unroll
    for (int v = 0; v < 4; v++) {
        int kr = b_kr + v * 8;
        cp_async16(bAddr + (kr * BPITCH + b_c4) * 4,
                   B + (size_t)(k0 + kr) * N + b_c4);
    }
}

__device__ __forceinline__ void gemm_body(
    const float* __restrict__ A, const float* __restrict__ B,
    float* __restrict__ C, int N, int K, uint32_t smem_base)
{
    const int tid  = threadIdx.x;
    const int wid  = tid >> 5;
    const int lane = tid & 31;
    const int g    = lane >> 2;
    const int tig  = lane & 3;

    const int warp_m = (wid & 1) * 64;
    const int warp_n = (wid >> 1) * 32;

    uint32_t* sm = (uint32_t*)__cvta_shared_to_generic(smem_base);

    const int a_row = tid >> 1;
    const int a_c4  = (tid & 1) << 4;
    const int b_kr  = tid >> 5;
    const int b_c4  = lane << 2;

    float acc[4][4][4];
    #pragma unroll
    for (int i = 0; i < 4; i++)
        #pragma unroll
        for (int j = 0; j < 4; j++)
            #pragma unroll
            for (int c = 0; c < 4; c++) acc[i][j][c] = 0.0f;

    const int niter = K >> 5;

    #pragma unroll
    for (int p = 0; p < NSTG - 1; p++) {
        uint32_t ab = smem_base + (p * STG) * 4;
        gemm_fill(A, B, K, N, p << 5, ab, ab + ASZ * 4, a_row, a_c4, b_kr, b_c4);
        cp_commit();
    }

    for (int i = 0; i < niter; i++) {
        cp_wait<NSTG - 2>();
        __syncthreads();

        const int ft = i + NSTG - 1;
        if (ft < niter) {
            const int fs = ft % NSTG;
            uint32_t ab = smem_base + (fs * STG) * 4;
            gemm_fill(A, B, K, N, ft << 5, ab, ab + ASZ * 4, a_row, a_c4, b_kr, b_c4);
        }
        cp_commit();

        const int cur = i % NSTG;
        const uint32_t* As = sm + cur * STG;
        const uint32_t* Bs = As + ASZ;

        #pragma unroll
        for (int ks = 0; ks < 4; ks++) {
            const int kk = ks * 8;
            uint32_t af[4][4];
            #pragma unroll
            for (int mt = 0; mt < 4; mt++) {
                int ar = warp_m + mt * 16 + g;
                af[mt][0] = As[ar * APITCH + kk + tig];
                af[mt][1] = As[(ar + 8) * APITCH + kk + tig];
                af[mt][2] = As[ar * APITCH + kk + tig + 4];
                af[mt][3] = As[(ar + 8) * APITCH + kk + tig + 4];
            }
            uint32_t bf[4][2];
            #pragma unroll
            for (int nt = 0; nt < 4; nt++) {
                int bc = warp_n + nt * 8 + g;
                bf[nt][0] = Bs[(kk + tig) * BPITCH + bc];
                bf[nt][1] = Bs[(kk + tig + 4) * BPITCH + bc];
            }
            #pragma unroll
            for (int mt = 0; mt < 4; mt++)
                #pragma unroll
                for (int nt = 0; nt < 4; nt++)
                    mma_tf32(acc[mt][nt], af[mt][0], af[mt][1], af[mt][2], af[mt][3],
                             bf[nt][0], bf[nt][1]);
        }
    }

    float* Cw = C + (size_t)warp_m * N + warp_n;
    #pragma unroll
    for (int mt = 0; mt < 4; mt++) {
        #pragma unroll
        for (int nt = 0; nt < 4; nt++) {
            int row = mt * 16 + g;
            int col = nt * 8 + 2 * tig;
            *(float2*)(Cw + (size_t)row * N + col) =
                make_float2(acc[mt][nt][0], acc[mt][nt][1]);
            *(float2*)(Cw + (size_t)(row + 8) * N + col) =
                make_float2(acc[mt][nt][2], acc[mt][nt][3]);
        }
    }
}

__global__ __launch_bounds__(256, 2)
void qkv_gemm_kernel(float* __restrict__ gq, float* __restrict__ gk,
                     float* __restrict__ gv) {
    extern __shared__ uint32_t smraw[];
    uint32_t smem_base = (uint32_t)__cvta_generic_to_shared(smraw);

    const int bx = blockIdx.x;
    const int by = blockIdx.y;

    const float* Bsel;
    float* Csel;
    int Nsel, colb;
    if (bx < 16)      { Bsel = g_wqt; Csel = gq; Nsel = 2048; colb = bx * 128; }
    else if (bx < 20) { Bsel = g_wkt; Csel = gk; Nsel = 512;  colb = (bx - 16) * 128; }
    else              { Bsel = g_wvt; Csel = gv; Nsel = 512;  colb = (bx - 20) * 128; }

    gemm_body(g_xt + (size_t)by * 128 * DD, Bsel + colb,
              Csel + (size_t)by * 128 * Nsel + colb, Nsel, DD, smem_base);
}

__global__ __launch_bounds__(256, 2)
void wo_gemm_kernel(float* __restrict__ C) {
    extern __shared__ uint32_t smraw[];
    uint32_t smem_base = (uint32_t)__cvta_generic_to_shared(smraw);
    gemm_body(g_o + (size_t)blockIdx.y * 128 * DD,
              g_wot + blockIdx.x * 128,
              C + (size_t)blockIdx.y * 128 * DD + blockIdx.x * 128,
              DD, DD, smem_base);
}

// ---------------------------------------------------------------------------
// RoPE in-place on g_q (scale+tf32 folded), g_k (tf32 folded), g_v (tf32 pass)
// ---------------------------------------------------------------------------
#define LOG2_THETA_OVER_HALF 0.20762050593046128f   // log2(10000)/64
#define ROPE_TOTQ (BB*TT*NH*64)
#define ROPE_TOTK (BB*TT*NKV*64)
#define ROPE_TOTV (BB*TT*NKV*HDIM)
#define ROPE_TOT  (ROPE_TOTQ + ROPE_TOTK + ROPE_TOTV)

__global__ __launch_bounds__(256)
void rope_kernel() {
    const float scale = 0.08838834764831845f;  // 1/sqrt(128)
    int idx = blockIdx.x * blockDim.x + threadIdx.x;
    if (idx < ROPE_TOTQ) {
        int d  = idx & 63;
        int h  = (idx >> 6) % NH;
        int bt = idx / (64 * NH);
        int t  = bt & (TT - 1);
        float inv = exp2f(-(float)d * LOG2_THETA_OVER_HALF);
        float ang = (float)t * inv;
        float s, c;
        sincosf(ang, &s, &c);
        float* p = g_q + (size_t)bt * (NH * HDIM) + h * HDIM;
        float x1 = p[d], x2 = p[d + 64];
        p[d]      = __uint_as_float(f32_to_tf32((x1 * c - x2 * s) * scale));
        p[d + 64] = __uint_as_float(f32_to_tf32((x2 * c + x1 * s) * scale));
    } else if (idx < ROPE_TOTQ + ROPE_TOTK) {
        int j  = idx - ROPE_TOTQ;
        int d  = j & 63;
        int h  = (j >> 6) % NKV;
        int bt = j / (64 * NKV);
        int t  = bt & (TT - 1);
        float inv = exp2f(-(float)d * LOG2_THETA_OVER_HALF);
        float ang = (float)t * inv;
        float s, c;
        sincosf(ang, &s, &c);
        float* p = g_k + (size_t)bt * (NKV * HDIM) + h * HDIM;
        float x1 = p[d], x2 = p[d + 64];
        p[d]      = __uint_as_float(f32_to_tf32(x1 * c - x2 * s));
        p[d + 64] = __uint_as_float(f32_to_tf32(x2 * c + x1 * s));
    } else if (idx < ROPE_TOT) {
        int j = idx - ROPE_TOTQ - ROPE_TOTK;
        g_v[j] = __uint_as_float(f32_to_tf32(g_v[j]));
    }
}

// ---------------------------------------------------------------------------
// Tensor-core flash attention (tf32 mma.sync), BM=128, BN=64, HD=128.
// 8 warps, warp owns 16 rows. Bank-conflict-free pitches:
//   Q/K (loads row=..+g, col=..+tig): pitch 132 (== 4 mod 32)
//   V   (loads row=..+tig, col=..+g): pitch 136 (== 8 mod 32)
//   P   (loads row=..+g, col=..+tig): pitch 68  (== 4 mod 32)
// smem words: Qs[128][132]=16896 | Ks[64][132]=8448 | Vs[2][64][136]=17408 |
//             Ps[128][68]=8704 | mask[2][64]=128 -> 51584 words = 206336 B
// ---------------------------------------------------------------------------
#define QKP 132
#define VKP 136
#define PP  68
#define QS_OFF   0
#define KS_OFF   16896
#define VS_OFF   25344
#define PS_OFF   42752
#define MASK_OFF 51456
#define ATTN_SMEM_BYTES (51584 * 4)

__global__ __launch_bounds__(256, 1)
void attn_mma_kernel(const int* __restrict__ mask, const int* __restrict__ causal_p) {
    extern __shared__ uint32_t sm[];
    const uint32_t smem_base = (uint32_t)__cvta_generic_to_shared(sm);
    uint32_t* Qs    = sm + QS_OFF;
    uint32_t* Ks    = sm + KS_OFF;
    uint32_t* Ps    = sm + PS_OFF;
    int*      maskS = (int*)(sm + MASK_OFF);

    const int tid  = threadIdx.x;
    const int wid  = tid >> 5;
    const int lane = tid & 31;
    const int g    = lane >> 2;
    const int tig  = lane & 3;

    const int qb  = (gridDim.x - 1) - blockIdx.x;   // LPT: long CTAs first
    const int h   = blockIdx.y;
    const int b   = blockIdx.z;
    const int kvh = h >> 2;
    const int causal = causal_p[0];

    const float* qbase = g_q + ((size_t)b * TT + qb * 128) * 2048 + h * HDIM;
    const float* kbase = g_k + (size_t)b * TT * 512 + kvh * HDIM;
    const float* vbase = g_v + (size_t)b * TT * 512 + kvh * HDIM;
    const int*   mbase = mask + b * TT;

    // ---- prologue: async fill Q (whole), K0, V0 buf0, mask0 ----
    #pragma unroll
    for (int it = 0; it < 16; it++) {
        int task = tid + 256 * it;
        int r = task >> 5;
        int c = (task & 31) << 2;
        cp_async16(smem_base + (QS_OFF + r * QKP + c) * 4,
                   qbase + (size_t)r * 2048 + c);
    }
    #pragma unroll
    for (int it = 0; it < 8; it++) {
        int task = tid + 256 * it;
        int r = task >> 5;
        int c = (task & 31) << 2;
        cp_async16(smem_base + (KS_OFF + r * QKP + c) * 4,
                   kbase + (size_t)r * 512 + c);
        cp_async16(smem_base + (VS_OFF + r * VKP + c) * 4,
                   vbase + (size_t)r * 512 + c);
    }
    if (tid < 64)
        cp_async4(smem_base + (MASK_OFF + tid) * 4, mbase + tid);
    cp_commit();

    const int r0  = 16 * wid + g;
    const int r1  = r0 + 8;
    const int qg0 = qb * 128 + r0;
    const int qg1 = qb * 128 + r1;

    float accO[16][4];
    #pragma unroll
    for (int nt = 0; nt < 16; nt++)
        #pragma unroll
        for (int c = 0; c < 4; c++) accO[nt][c] = 0.0f;

    float m0 = -1e30f, m1 = -1e30f, l0 = 0.0f, l1 = 0.0f;

    const int kbmax = causal ? (2 * qb + 1) : (TT / 64 - 1);

    for (int kb = 0; kb <= kbmax; kb++) {
        const int kr0 = kb * 64;
        const int cbuf = kb & 1;

        cp_wait<0>();          // K[kb], V[kb], mask[kb] (and Q on kb=0) arrived
        __syncthreads();       // visible to all threads; prior PV done

        // ---- S = Q @ K^T : warp computes 16 x 64 ----
        float sacc[8][4];
        #pragma unroll
        for (int nt = 0; nt < 8; nt++)
            #pragma unroll
            for (int c = 0; c < 4; c++) sacc[nt][c] = 0.0f;

        #pragma unroll
        for (int ks = 0; ks < 16; ks++) {
            const uint32_t* qr = &Qs[r0 * QKP + ks * 8 + tig];
            uint32_t a0 = qr[0];
            uint32_t a2 = qr[4];
            uint32_t a1 = qr[8 * QKP];
            uint32_t a3 = qr[8 * QKP + 4];
            #pragma unroll
            for (int nt = 0; nt < 8; nt++) {
                const uint32_t* kr = &Ks[(8 * nt + g) * QKP + ks * 8 + tig];
                mma_tf32(sacc[nt], a0, a1, a2, a3, kr[0], kr[4]);
            }
        }
        __syncthreads();       // all warps done reading Ks

        // ---- prefetch K[kb+1], V[kb+1] (alt buf), mask[kb+1] ----
        if (kb < kbmax) {
            const int nr0 = kr0 + 64;
            const int nbuf = (kb + 1) & 1;
            #pragma unroll
            for (int it = 0; it < 8; it++) {
                int task = tid + 256 * it;
                int r = task >> 5;
                int c = (task & 31) << 2;
                cp_async16(smem_base + (KS_OFF + r * QKP + c) * 4,
                           kbase + (size_t)(nr0 + r) * 512 + c);
                cp_async16(smem_base + (VS_OFF + nbuf * 8704 + r * VKP + c) * 4,
                           vbase + (size_t)(nr0 + r) * 512 + c);
            }
            if (tid < 64)
                cp_async4(smem_base + (MASK_OFF + nbuf * 64 + tid) * 4,
                          mbase + nr0 + tid);
        }
        cp_commit();

        // ---- mask + warp-local row max ----
        const int* mcur = maskS + cbuf * 64;
        float lm0 = -1e30f, lm1 = -1e30f;
        #pragma unroll
        for (int nt = 0; nt < 8; nt++) {
            #pragma unroll
            for (int e = 0; e < 2; e++) {
                int c  = 8 * nt + 2 * tig + e;
                int kg = kr0 + c;
                bool mz = (mcur[c] == 0);
                if (mz || (causal && kg > qg0)) sacc[nt][e]     = -1e30f;
                if (mz || (causal && kg > qg1)) sacc[nt][e + 2] = -1e30f;
                lm0 = fmaxf(lm0, sacc[nt][e]);
                lm1 = fmaxf(lm1, sacc[nt][e + 2]);
            }
        }
        lm0 = fmaxf(lm0, __shfl_xor_sync(0xffffffffu, lm0, 1));
        lm0 = fmaxf(lm0, __shfl_xor_sync(0xffffffffu, lm0, 2));
        lm1 = fmaxf(lm1, __shfl_xor_sync(0xffffffffu, lm1, 1));
        lm1 = fmaxf(lm1, __shfl_xor_sync(0xffffffffu, lm1, 2));

        float mn0 = fmaxf(m0, lm0);
        float mn1 = fmaxf(m1, lm1);
        float esc0 = __expf(m0 - mn0);
        float esc1 = __expf(m1 - mn1);

        float ls0 = 0.0f, ls1 = 0.0f;
        #pragma unroll
        for (int nt = 0; nt < 8; nt++) {
            float p0 = __expf(sacc[nt][0] - mn0);
            float p1 = __expf(sacc[nt][1] - mn0);
            float p2 = __expf(sacc[nt][2] - mn1);
            float p3 = __expf(sacc[nt][3] - mn1);
            ls0 += p0 + p1;
            ls1 += p2 + p3;
            int c = 8 * nt + 2 * tig;
            uint32_t* d0 = &Ps[r0 * PP + c];
            uint32_t* d1 = &Ps[r1 * PP + c];
            d0[0] = f32_to_tf32(p0);
            d0[1] = f32_to_tf32(p1);
            d1[0] = f32_to_tf32(p2);
            d1[1] = f32_to_tf32(p3);
        }
        ls0 += __shfl_xor_sync(0xffffffffu, ls0, 1);
        ls0 += __shfl_xor_sync(0xffffffffu, ls0, 2);
        ls1 += __shfl_xor_sync(0xffffffffu, ls1, 1);
        ls1 += __shfl_xor_sync(0xffffffffu, ls1, 2);

        l0 = l0 * esc0 + ls0;
        l1 = l1 * esc1 + ls1;
        m0 = mn0;
        m1 = mn1;

        #pragma unroll
        for (int nt = 0; nt < 16; nt++) {
            accO[nt][0] *= esc0; accO[nt][1] *= esc0;
            accO[nt][2] *= esc1; accO[nt][3] *= esc1;
        }
        __syncwarp();   // P visible to own warp

        // ---- O += P @ V (current buffer) ----
        const uint32_t* Vc = sm + VS_OFF + cbuf * 8704;
        #pragma unroll
        for (int ks = 0; ks < 8; ks++) {
            const uint32_t* pr = &Ps[r0 * PP + ks * 8 + tig];
            uint32_t a0 = pr[0];
            uint32_t a2 = pr[4];
            uint32_t a1 = pr[8 * PP];
            uint32_t a3 = pr[8 * PP + 4];
            #pragma unroll
            for (int nt = 0; nt < 16; nt++) {
                const uint32_t* vr = &Vc[(ks * 8 + tig) * VKP + 8 * nt + g];
                mma_tf32(accO[nt], a0, a1, a2, a3, vr[0], vr[4 * VKP]);
            }
        }
    }

    float invl0 = 1.0f / l0;
    float invl1 = 1.0f / l1;
    float* ob0 = g_o + ((size_t)b * TT + qb * 128 + r0) * 2048 + h * HDIM + 2 * tig;
    float* ob1 = g_o + ((size_t)b * TT + qb * 128 + r1) * 2048 + h * HDIM + 2 * tig;
    #pragma unroll
    for (int nt = 0; nt < 16; nt++) {
        *(float2*)(ob0 + 8 * nt) = make_float2(
            __uint_as_float(f32_to_tf32(accO[nt][0] * invl0)),
            __uint_as_float(f32_to_tf32(accO[nt][1] * invl0)));
        *(float2*)(ob1 + 8 * nt) = make_float2(
            __uint_as_float(f32_to_tf32(accO[nt][2] * invl1)),
            __uint_as_float(f32_to_tf32(accO[nt][3] * invl1)));
    }
}

// ---------------------------------------------------------------------------
extern "C" void kernel_launch(void* const* d_in, const int* in_sizes, int n_in,
                              void* d_out, int out_size) {
    const float* x      = (const float*)d_in[0];
    const int*   mask   = (const int*)d_in[1];
    const int*   causal = (const int*)d_in[2];
    const float* wq     = (const float*)d_in[3];
    const float* wk     = (const float*)d_in[4];
    const float* wv     = (const float*)d_in[5];
    const float* wo     = (const float*)d_in[6];
    float* out = (float*)d_out;

    float *gq, *gk, *gv, *xt, *wqt, *wkt, *wvt, *wot;
    cudaGetSymbolAddress((void**)&gq,  g_q);
    cudaGetSymbolAddress((void**)&gk,  g_k);
    cudaGetSymbolAddress((void**)&gv,  g_v);
    cudaGetSymbolAddress((void**)&xt,  g_xt);
    cudaGetSymbolAddress((void**)&wqt, g_wqt);
    cudaGetSymbolAddress((void**)&wkt, g_wkt);
    cudaGetSymbolAddress((void**)&wvt, g_wvt);
    cudaGetSymbolAddress((void**)&wot, g_wot);

    const int M = BB * TT;  // 4096

    cudaFuncSetAttribute(qkv_gemm_kernel, cudaFuncAttributeMaxDynamicSharedMemorySize,
                         GEMM_SMEM_BYTES);
    cudaFuncSetAttribute(wo_gemm_kernel, cudaFuncAttributeMaxDynamicSharedMemorySize,
                         GEMM_SMEM_BYTES);
    cudaFuncSetAttribute(attn_mma_kernel, cudaFuncAttributeMaxDynamicSharedMemorySize,
                         ATTN_SMEM_BYTES);

    // Pre-convert operands to tf32 (single fused launch)
    cvt_all_kernel<<<(CVT_N4 + 255) / 256, 256>>>(
        (const float4*)x,  (const float4*)wq, (const float4*)wk,
        (const float4*)wv, (const float4*)wo,
        (float4*)xt, (float4*)wqt, (float4*)wkt, (float4*)wvt, (float4*)wot);

    // Fused QKV projection
    qkv_gemm_kernel<<<dim3(24, M / 128), 256, GEMM_SMEM_BYTES>>>(gq, gk, gv);

    // RoPE (+ tf32 rounding of q (scaled), k, v)
    rope_kernel<<<(ROPE_TOT + 255) / 256, 256>>>();

    // Attention (mma.sync tensor cores), BM=128, conflict-free pitches
    attn_mma_kernel<<<dim3(TT / 128, NH, BB), 256, ATTN_SMEM_BYTES>>>(mask, causal);

    // Output projection
    wo_gemm_kernel<<<dim3(DD / 128, M / 128), 256, GEMM_SMEM_BYTES>>>(out);
}

// round 12
// speedup vs baseline: 1.9386x; 1.7599x over previous
#include <cuda_runtime.h>
#include <cuda_fp16.h>
#include <math.h>
#include <stdint.h>

#define BB   2
#define TT   2048
#define DD   2048
#define NH   16
#define NKV  4
#define HDIM 128

// fp32 GEMM outputs (pre-rope)
__device__ float  g_q[BB*TT*NH*HDIM];
__device__ float  g_k[BB*TT*NKV*HDIM];
__device__ float  g_v[BB*TT*NKV*HDIM];
// fp16 operands
__device__ __half g_xh [BB*TT*DD];          // x fp16 [M][K]
__device__ __half g_wqh[NH*HDIM*DD];        // weights transposed [N][K]
__device__ __half g_wkh[NKV*HDIM*DD];
__device__ __half g_wvh[NKV*HDIM*DD];
__device__ __half g_woh[DD*DD];
__device__ __half g_qh [BB*TT*NH*HDIM];     // rope'd q (scaled) fp16
__device__ __half g_kh [BB*TT*NKV*HDIM];    // rope'd k fp16
__device__ __half g_vt [BB*NKV*HDIM*TT];    // v transposed [bkv][hd][t] fp16
__device__ __half g_oh [BB*TT*NH*HDIM];     // attention out fp16

__device__ __forceinline__ void mma_f16(float c[4],
                                        uint32_t a0, uint32_t a1, uint32_t a2, uint32_t a3,
                                        uint32_t b0, uint32_t b1) {
    asm volatile(
        "mma.sync.aligned.m16n8k16.row.col.f32.f16.f16.f32 "
        "{%0,%1,%2,%3}, {%4,%5,%6,%7}, {%8,%9}, {%0,%1,%2,%3};\n"
        : "+f"(c[0]), "+f"(c[1]), "+f"(c[2]), "+f"(c[3])
        : "r"(a0), "r"(a1), "r"(a2), "r"(a3), "r"(b0), "r"(b1));
}

__device__ __forceinline__ void cp_async16(uint32_t smem_addr, const void* gptr) {
    asm volatile("cp.async.cg.shared.global [%0], [%1], 16;\n"
                 :: "r"(smem_addr), "l"(gptr));
}
__device__ __forceinline__ void cp_async4(uint32_t smem_addr, const void* gptr) {
    asm volatile("cp.async.ca.shared.global [%0], [%1], 4;\n"
                 :: "r"(smem_addr), "l"(gptr));
}
__device__ __forceinline__ void cp_commit() {
    asm volatile("cp.async.commit_group;\n" ::: "memory");
}
template <int N>
__device__ __forceinline__ void cp_wait() {
    asm volatile("cp.async.wait_group %0;\n" :: "n"(N) : "memory");
}

// ---------------------------------------------------------------------------
// x -> fp16 elementwise
// ---------------------------------------------------------------------------
__global__ __launch_bounds__(256)
void cvt_x_kernel(const float4* __restrict__ src, __half2* __restrict__ dst, int n4) {
    int i = blockIdx.x * blockDim.x + threadIdx.x;
    if (i < n4) {
        float4 f = src[i];
        dst[2 * i]     = __floats2half2_rn(f.x, f.y);
        dst[2 * i + 1] = __floats2half2_rn(f.z, f.w);
    }
}

// transpose + cvt: src [K][N] fp32 -> dst [N][K] fp16
__global__ __launch_bounds__(256)
void cvt_t_kernel(const float* __restrict__ src, __half* __restrict__ dst,
                  int K, int N) {
    __shared__ float tile[32][33];
    const int n0 = blockIdx.x * 32;
    const int k0 = blockIdx.y * 32;
    const int tx = threadIdx.x & 31;
    const int ty = threadIdx.x >> 5;   // 0..7
    #pragma unroll
    for (int r = 0; r < 32; r += 8)
        tile[r + ty][tx] = src[(size_t)(k0 + r + ty) * N + n0 + tx];
    __syncthreads();
    #pragma unroll
    for (int r = 0; r < 32; r += 8)
        dst[(size_t)(n0 + r + ty) * K + k0 + tx] = __float2half_rn(tile[tx][r + ty]);
}

// V transpose + cvt: g_v fp32 [b*T][512] -> g_vt fp16 [(b*NKV+kv)][128][2048]
__global__ __launch_bounds__(256)
void vt_kernel() {
    __shared__ float tile[32][33];
    const int bk = blockIdx.z;
    const int b  = bk >> 2;
    const int kv = bk & 3;
    const int t0 = blockIdx.x * 32;
    const int d0 = blockIdx.y * 32;
    const int tx = threadIdx.x & 31;
    const int ty = threadIdx.x >> 5;
    #pragma unroll
    for (int r = 0; r < 32; r += 8)
        tile[r + ty][tx] =
            g_v[((size_t)b * TT + t0 + r + ty) * 512 + kv * 128 + d0 + tx];
    __syncthreads();
    __half* dst = g_vt + (size_t)bk * HDIM * TT;
    #pragma unroll
    for (int r = 0; r < 32; r += 8)
        dst[(size_t)(d0 + r + ty) * TT + t0 + tx] = __float2half_rn(tile[tx][r + ty]);
}

// ---------------------------------------------------------------------------
// fp16 mma.sync GEMM: 256 threads (8 warps), warp tile 64x32, BK=32 halves.
// Both operands K-major fp16; word pitch 20 (== 4 mod 32, conflict-free).
// 3-stage cp.async, one sync per iteration. fp32 accumulate & output.
// ---------------------------------------------------------------------------
#define GP   20
#define GASZ (128 * GP)
#define GSTG (2 * GASZ)
#define NSTG 3
#define GEMM_SMEM_BYTES (NSTG * GSTG * 4)

__device__ __forceinline__ void gemm_fill(const __half* __restrict__ A,
                                          const __half* __restrict__ Bt,
                                          int K, int k0,
                                          uint32_t aAddr, uint32_t bAddr, int tid) {
    #pragma unroll
    for (int v = 0; v < 2; v++) {
        int task = tid + 256 * v;
        int r  = task >> 2;
        int ch = task & 3;
        cp_async16(aAddr + (r * GP + ch * 4) * 4, A  + (size_t)r * K + k0 + ch * 8);
        cp_async16(bAddr + (r * GP + ch * 4) * 4, Bt + (size_t)r * K + k0 + ch * 8);
    }
}

__device__ __forceinline__ void gemm_body(
    const __half* __restrict__ A,    // [128+][K] K-major (row block applied)
    const __half* __restrict__ Bt,   // [128+][K] K-major (col block applied)
    float* __restrict__ C, int N, int K, uint32_t smem_base)
{
    const int tid  = threadIdx.x;
    const int wid  = tid >> 5;
    const int lane = tid & 31;
    const int g    = lane >> 2;
    const int tig  = lane & 3;

    const int warp_m = (wid & 1) * 64;
    const int warp_n = (wid >> 1) * 32;

    uint32_t* sm = (uint32_t*)__cvta_shared_to_generic(smem_base);

    float acc[4][4][4];
    #pragma unroll
    for (int i = 0; i < 4; i++)
        #pragma unroll
        for (int j = 0; j < 4; j++)
            #pragma unroll
            for (int c = 0; c < 4; c++) acc[i][j][c] = 0.0f;

    const int niter = K >> 5;

    #pragma unroll
    for (int p = 0; p < NSTG - 1; p++) {
        uint32_t ab = smem_base + (p * GSTG) * 4;
        gemm_fill(A, Bt, K, p << 5, ab, ab + GASZ * 4, tid);
        cp_commit();
    }

    for (int i = 0; i < niter; i++) {
        cp_wait<NSTG - 2>();
        __syncthreads();

        const int ft = i + NSTG - 1;
        if (ft < niter) {
            const int fs = ft % NSTG;
            uint32_t ab = smem_base + (fs * GSTG) * 4;
            gemm_fill(A, Bt, K, ft << 5, ab, ab + GASZ * 4, tid);
        }
        cp_commit();

        const int cur = i % NSTG;
        const uint32_t* As = sm + cur * GSTG;
        const uint32_t* Bs = As + GASZ;

        #pragma unroll
        for (int ks = 0; ks < 2; ks++) {
            const int kk = ks * 8;
            uint32_t af[4][4];
            #pragma unroll
            for (int mt = 0; mt < 4; mt++) {
                int ar = warp_m + mt * 16 + g;
                af[mt][0] = As[ar * GP + kk + tig];
                af[mt][1] = As[(ar + 8) * GP + kk + tig];
                af[mt][2] = As[ar * GP + kk + tig + 4];
                af[mt][3] = As[(ar + 8) * GP + kk + tig + 4];
            }
            uint32_t bf[4][2];
            #pragma unroll
            for (int nt = 0; nt < 4; nt++) {
                int br = warp_n + nt * 8 + g;
                bf[nt][0] = Bs[br * GP + kk + tig];
                bf[nt][1] = Bs[br * GP + kk + tig + 4];
            }
            #pragma unroll
            for (int mt = 0; mt < 4; mt++)
                #pragma unroll
                for (int nt = 0; nt < 4; nt++)
                    mma_f16(acc[mt][nt], af[mt][0], af[mt][1], af[mt][2], af[mt][3],
                            bf[nt][0], bf[nt][1]);
        }
    }

    float* Cw = C + (size_t)warp_m * N + warp_n;
    #pragma unroll
    for (int mt = 0; mt < 4; mt++) {
        #pragma unroll
        for (int nt = 0; nt < 4; nt++) {
            int row = mt * 16 + g;
            int col = nt * 8 + 2 * tig;
            *(float2*)(Cw + (size_t)row * N + col) =
                make_float2(acc[mt][nt][0], acc[mt][nt][1]);
            *(float2*)(Cw + (size_t)(row + 8) * N + col) =
                make_float2(acc[mt][nt][2], acc[mt][nt][3]);
        }
    }
}

__global__ __launch_bounds__(256, 2)
void qkv_gemm_kernel(float* __restrict__ gq, float* __restrict__ gk,
                     float* __restrict__ gv) {
    extern __shared__ uint32_t smraw[];
    uint32_t smem_base = (uint32_t)__cvta_generic_to_shared(smraw);

    const int bx = blockIdx.x;
    const int by = blockIdx.y;

    const __half* Bsel;
    float* Csel;
    int Nsel, colb;
    if (bx < 16)      { Bsel = g_wqh; Csel = gq; Nsel = 2048; colb = bx * 128; }
    else if (bx < 20) { Bsel = g_wkh; Csel = gk; Nsel = 512;  colb = (bx - 16) * 128; }
    else              { Bsel = g_wvh; Csel = gv; Nsel = 512;  colb = (bx - 20) * 128; }

    gemm_body(g_xh + (size_t)by * 128 * DD,
              Bsel + (size_t)colb * DD,
              Csel + (size_t)by * 128 * Nsel + colb, Nsel, DD, smem_base);
}

__global__ __launch_bounds__(256, 2)
void wo_gemm_kernel(float* __restrict__ C) {
    extern __shared__ uint32_t smraw[];
    uint32_t smem_base = (uint32_t)__cvta_generic_to_shared(smraw);
    gemm_body(g_oh + (size_t)blockIdx.y * 128 * DD,
              g_woh + (size_t)blockIdx.x * 128 * DD,
              C + (size_t)blockIdx.y * 128 * DD + blockIdx.x * 128,
              DD, DD, smem_base);
}

// ---------------------------------------------------------------------------
// RoPE: g_q fp32 -> g_qh fp16 (scaled), g_k fp32 -> g_kh fp16
// ---------------------------------------------------------------------------
#define LOG2_THETA_OVER_HALF 0.20762050593046128f   // log2(10000)/64
#define ROPE_TOTQ (BB*TT*NH*64)
#define ROPE_TOTK (BB*TT*NKV*64)
#define ROPE_TOT  (ROPE_TOTQ + ROPE_TOTK)

__global__ __launch_bounds__(256)
void rope_kernel() {
    const float scale = 0.08838834764831845f;  // 1/sqrt(128)
    int idx = blockIdx.x * blockDim.x + threadIdx.x;
    if (idx < ROPE_TOTQ) {
        int d  = idx & 63;
        int h  = (idx >> 6) % NH;
        int bt = idx / (64 * NH);
        int t  = bt & (TT - 1);
        float inv = exp2f(-(float)d * LOG2_THETA_OVER_HALF);
        float ang = (float)t * inv;
        float s, c;
        sincosf(ang, &s, &c);
        const float* p = g_q + (size_t)bt * (NH * HDIM) + h * HDIM;
        __half* o = g_qh + (size_t)bt * (NH * HDIM) + h * HDIM;
        float x1 = p[d], x2 = p[d + 64];
        o[d]      = __float2half_rn((x1 * c - x2 * s) * scale);
        o[d + 64] = __float2half_rn((x2 * c + x1 * s) * scale);
    } else if (idx < ROPE_TOT) {
        int j  = idx - ROPE_TOTQ;
        int d  = j & 63;
        int h  = (j >> 6) % NKV;
        int bt = j / (64 * NKV);
        int t  = bt & (TT - 1);
        float inv = exp2f(-(float)d * LOG2_THETA_OVER_HALF);
        float ang = (float)t * inv;
        float s, c;
        sincosf(ang, &s, &c);
        const float* p = g_k + (size_t)bt * (NKV * HDIM) + h * HDIM;
        __half* o = g_kh + (size_t)bt * (NKV * HDIM) + h * HDIM;
        float x1 = p[d], x2 = p[d + 64];
        o[d]      = __float2half_rn(x1 * c - x2 * s);
        o[d + 64] = __float2half_rn(x2 * c + x1 * s);
    }
}

// ---------------------------------------------------------------------------
// fp16 flash attention, BM=128, BN=64, HD=128, 8 warps (16 rows each).
// Word pitches (uint32): Q/K 68, Vt 36, P 36  (all == 4 mod 32, conflict-free).
// smem words: Qs[128][68]=8704 | Ks[64][68]=4352 | Vt[2][128][36]=9216 |
//             Ps[128][36]=4608 | mask[2][64]=128  -> 27008 words = 108032 B
// ---------------------------------------------------------------------------
#define QKP 68
#define VTP 36
#define PPW 36
#define QS_OFF   0
#define KS_OFF   8704
#define VS_OFF   13056
#define PS_OFF   22272
#define MASK_OFF 26880
#define ATTN_SMEM_BYTES (27008 * 4)

__global__ __launch_bounds__(256, 1)
void attn_mma_kernel(const int* __restrict__ mask, const int* __restrict__ causal_p) {
    extern __shared__ uint32_t sm[];
    const uint32_t smem_base = (uint32_t)__cvta_generic_to_shared(sm);
    uint32_t* Qs    = sm + QS_OFF;
    uint32_t* Ks    = sm + KS_OFF;
    uint32_t* Ps    = sm + PS_OFF;
    int*      maskS = (int*)(sm + MASK_OFF);

    const int tid  = threadIdx.x;
    const int wid  = tid >> 5;
    const int lane = tid & 31;
    const int g    = lane >> 2;
    const int tig  = lane & 3;

    const int qb  = (gridDim.x - 1) - blockIdx.x;   // LPT
    const int h   = blockIdx.y;
    const int b   = blockIdx.z;
    const int kvh = h >> 2;
    const int causal = causal_p[0];

    const __half* qbase = g_qh + ((size_t)b * TT + qb * 128) * 2048 + h * HDIM;
    const __half* kbase = g_kh + (size_t)b * TT * 512 + kvh * HDIM;
    const __half* vtbase = g_vt + (size_t)(b * NKV + kvh) * HDIM * TT;
    const int*   mbase = mask + b * TT;

    // ---- prologue: Q whole, K0, Vt0 (buf0), mask0 ----
    #pragma unroll
    for (int it = 0; it < 8; it++) {
        int task = tid + 256 * it;            // 2048 chunks
        int r = task >> 4;
        int c = task & 15;
        cp_async16(smem_base + (QS_OFF + r * QKP + c * 4) * 4,
                   qbase + (size_t)r * 2048 + c * 8);
    }
    #pragma unroll
    for (int it = 0; it < 4; it++) {
        int task = tid + 256 * it;            // 1024 chunks
        int r = task >> 4;
        int c = task & 15;
        cp_async16(smem_base + (KS_OFF + r * QKP + c * 4) * 4,
                   kbase + (size_t)r * 512 + c * 8);
    }
    #pragma unroll
    for (int it = 0; it < 4; it++) {
        int task = tid + 256 * it;            // 1024 chunks (128 rows x 8)
        int r = task >> 3;
        int c = task & 7;
        cp_async16(smem_base + (VS_OFF + r * VTP + c * 4) * 4,
                   vtbase + (size_t)r * TT + c * 8);
    }
    if (tid < 64)
        cp_async4(smem_base + (MASK_OFF + tid) * 4, mbase + tid);
    cp_commit();

    const int r0  = 16 * wid + g;
    const int r1  = r0 + 8;
    const int qg0 = qb * 128 + r0;
    const int qg1 = qb * 128 + r1;

    float accO[16][4];
    #pragma unroll
    for (int nt = 0; nt < 16; nt++)
        #pragma unroll
        for (int c = 0; c < 4; c++) accO[nt][c] = 0.0f;

    float m0 = -1e30f, m1 = -1e30f, l0 = 0.0f, l1 = 0.0f;

    const int kbmax = causal ? (2 * qb + 1) : (TT / 64 - 1);

    for (int kb = 0; kb <= kbmax; kb++) {
        const int kr0 = kb * 64;
        const int cbuf = kb & 1;

        cp_wait<0>();
        __syncthreads();

        // ---- S = Q @ K^T : warp computes 16 x 64, k over 8 chunks of 16 ----
        float sacc[8][4];
        #pragma unroll
        for (int nt = 0; nt < 8; nt++)
            #pragma unroll
            for (int c = 0; c < 4; c++) sacc[nt][c] = 0.0f;

        #pragma unroll
        for (int ks = 0; ks < 8; ks++) {
            const uint32_t* qr = &Qs[r0 * QKP + ks * 8 + tig];
            uint32_t a0 = qr[0];
            uint32_t a2 = qr[4];
            uint32_t a1 = qr[8 * QKP];
            uint32_t a3 = qr[8 * QKP + 4];
            #pragma unroll
            for (int nt = 0; nt < 8; nt++) {
                const uint32_t* kr = &Ks[(8 * nt + g) * QKP + ks * 8 + tig];
                mma_f16(sacc[nt], a0, a1, a2, a3, kr[0], kr[4]);
            }
        }
        __syncthreads();       // Ks free

        // ---- prefetch K[kb+1], Vt[kb+1] (alt buf), mask[kb+1] ----
        if (kb < kbmax) {
            const int nr0 = kr0 + 64;
            const int nbuf = (kb + 1) & 1;
            #pragma unroll
            for (int it = 0; it < 4; it++) {
                int task = tid + 256 * it;
                int r = task >> 4;
                int c = task & 15;
                cp_async16(smem_base + (KS_OFF + r * QKP + c * 4) * 4,
                           kbase + (size_t)(nr0 + r) * 512 + c * 8);
            }
            #pragma unroll
            for (int it = 0; it < 4; it++) {
                int task = tid + 256 * it;
                int r = task >> 3;
                int c = task & 7;
                cp_async16(smem_base + (VS_OFF + nbuf * 4608 + r * VTP + c * 4) * 4,
                           vtbase + (size_t)r * TT + nr0 + c * 8);
            }
            if (tid < 64)
                cp_async4(smem_base + (MASK_OFF + nbuf * 64 + tid) * 4,
                          mbase + nr0 + tid);
        }
        cp_commit();

        // ---- mask + warp-local row max ----
        const int* mcur = maskS + cbuf * 64;
        float lm0 = -1e30f, lm1 = -1e30f;
        #pragma unroll
        for (int nt = 0; nt < 8; nt++) {
            #pragma unroll
            for (int e = 0; e < 2; e++) {
                int c  = 8 * nt + 2 * tig + e;
                int kg = kr0 + c;
                bool mz = (mcur[c] == 0);
                if (mz || (causal && kg > qg0)) sacc[nt][e]     = -1e30f;
                if (mz || (causal && kg > qg1)) sacc[nt][e + 2] = -1e30f;
                lm0 = fmaxf(lm0, sacc[nt][e]);
                lm1 = fmaxf(lm1, sacc[nt][e + 2]);
            }
        }
        lm0 = fmaxf(lm0, __shfl_xor_sync(0xffffffffu, lm0, 1));
        lm0 = fmaxf(lm0, __shfl_xor_sync(0xffffffffu, lm0, 2));
        lm1 = fmaxf(lm1, __shfl_xor_sync(0xffffffffu, lm1, 1));
        lm1 = fmaxf(lm1, __shfl_xor_sync(0xffffffffu, lm1, 2));

        float mn0 = fmaxf(m0, lm0);
        float mn1 = fmaxf(m1, lm1);
        float esc0 = __expf(m0 - mn0);
        float esc1 = __expf(m1 - mn1);

        // ---- p = exp(s - m), row sums, pack half2 into Ps ----
        float ls0 = 0.0f, ls1 = 0.0f;
        #pragma unroll
        for (int nt = 0; nt < 8; nt++) {
            float p0 = __expf(sacc[nt][0] - mn0);
            float p1 = __expf(sacc[nt][1] - mn0);
            float p2 = __expf(sacc[nt][2] - mn1);
            float p3 = __expf(sacc[nt][3] - mn1);
            ls0 += p0 + p1;
            ls1 += p2 + p3;
            int cw = 4 * nt + tig;   // word col (keys 8nt+2tig, +1)
            ((__half2*)Ps)[r0 * PPW + cw] = __floats2half2_rn(p0, p1);
            ((__half2*)Ps)[r1 * PPW + cw] = __floats2half2_rn(p2, p3);
        }
        ls0 += __shfl_xor_sync(0xffffffffu, ls0, 1);
        ls0 += __shfl_xor_sync(0xffffffffu, ls0, 2);
        ls1 += __shfl_xor_sync(0xffffffffu, ls1, 1);
        ls1 += __shfl_xor_sync(0xffffffffu, ls1, 2);

        l0 = l0 * esc0 + ls0;
        l1 = l1 * esc1 + ls1;
        m0 = mn0;
        m1 = mn1;

        #pragma unroll
        for (int nt = 0; nt < 16; nt++) {
            accO[nt][0] *= esc0; accO[nt][1] *= esc0;
            accO[nt][2] *= esc1; accO[nt][3] *= esc1;
        }
        __syncwarp();

        // ---- O += P @ V : k = 64 keys over 4 chunks of 16 ----
        const uint32_t* Vc = sm + VS_OFF + cbuf * 4608;
        #pragma unroll
        for (int ks = 0; ks < 4; ks++) {
            const uint32_t* pr = &Ps[r0 * PPW + ks * 8 + tig];
            uint32_t a0 = pr[0];
            uint32_t a2 = pr[4];
            uint32_t a1 = pr[8 * PPW];
            uint32_t a3 = pr[8 * PPW + 4];
            #pragma unroll
            for (int nt = 0; nt < 16; nt++) {
                const uint32_t* vr = &Vc[(8 * nt + g) * VTP + ks * 8 + tig];
                mma_f16(accO[nt], a0, a1, a2, a3, vr[0], vr[4]);
            }
        }
    }

    // ---- epilogue: normalize, write fp16 ----
    float invl0 = 1.0f / l0;
    float invl1 = 1.0f / l1;
    __half2* oh0 = (__half2*)(g_oh + ((size_t)b * TT + qb * 128 + r0) * 2048 + h * HDIM);
    __half2* oh1 = (__half2*)(g_oh + ((size_t)b * TT + qb * 128 + r1) * 2048 + h * HDIM);
    #pragma unroll
    for (int nt = 0; nt < 16; nt++) {
        oh0[4 * nt + tig] = __floats2half2_rn(accO[nt][0] * invl0, accO[nt][1] * invl0);
        oh1[4 * nt + tig] = __floats2half2_rn(accO[nt][2] * invl1, accO[nt][3] * invl1);
    }
}

// ---------------------------------------------------------------------------
extern "C" void kernel_launch(void* const* d_in, const int* in_sizes, int n_in,
                              void* d_out, int out_size) {
    const float* x      = (const float*)d_in[0];
    const int*   mask   = (const int*)d_in[1];
    const int*   causal = (const int*)d_in[2];
    const float* wq     = (const float*)d_in[3];
    const float* wk     = (const float*)d_in[4];
    const float* wv     = (const float*)d_in[5];
    const float* wo     = (const float*)d_in[6];
    float* out = (float*)d_out;

    float *gq, *gk, *gv;
    __half *xh, *wqh, *wkh, *wvh, *woh;
    cudaGetSymbolAddress((void**)&gq,  g_q);
    cudaGetSymbolAddress((void**)&gk,  g_k);
    cudaGetSymbolAddress((void**)&gv,  g_v);
    cudaGetSymbolAddress((void**)&xh,  g_xh);
    cudaGetSymbolAddress((void**)&wqh, g_wqh);
    cudaGetSymbolAddress((void**)&wkh, g_wkh);
    cudaGetSymbolAddress((void**)&wvh, g_wvh);
    cudaGetSymbolAddress((void**)&woh, g_woh);

    const int M = BB * TT;  // 4096

    cudaFuncSetAttribute(qkv_gemm_kernel, cudaFuncAttributeMaxDynamicSharedMemorySize,
                         GEMM_SMEM_BYTES);
    cudaFuncSetAttribute(wo_gemm_kernel, cudaFuncAttributeMaxDynamicSharedMemorySize,
                         GEMM_SMEM_BYTES);
    cudaFuncSetAttribute(attn_mma_kernel, cudaFuncAttributeMaxDynamicSharedMemorySize,
                         ATTN_SMEM_BYTES);

    // x -> fp16; weights -> transposed fp16
    {
        int n4 = (M * DD) / 4;
        cvt_x_kernel<<<(n4 + 255) / 256, 256>>>((const float4*)x, (__half2*)xh, n4);
        cvt_t_kernel<<<dim3(2048 / 32, 2048 / 32), 256>>>(wq, wqh, 2048, 2048);
        cvt_t_kernel<<<dim3(512 / 32,  2048 / 32), 256>>>(wk, wkh, 2048, 512);
        cvt_t_kernel<<<dim3(512 / 32,  2048 / 32), 256>>>(wv, wvh, 2048, 512);
        cvt_t_kernel<<<dim3(2048 / 32, 2048 / 32), 256>>>(wo, woh, 2048, 2048);
    }

    // Fused QKV projection (fp16 in, fp32 out)
    qkv_gemm_kernel<<<dim3(24, M / 128), 256, GEMM_SMEM_BYTES>>>(gq, gk, gv);

    // RoPE -> fp16 q (scaled), k
    rope_kernel<<<(ROPE_TOT + 255) / 256, 256>>>();

    // V transpose + cvt -> g_vt fp16
    vt_kernel<<<dim3(TT / 32, HDIM / 32, BB * NKV), 256>>>();

    // Attention (fp16 mma)
    attn_mma_kernel<<<dim3(TT / 128, NH, BB), 256, ATTN_SMEM_BYTES>>>(mask, causal);

    // Output projection (fp16 in, fp32 out)
    wo_gemm_kernel<<<dim3(DD / 128, M / 128), 256, GEMM_SMEM_BYTES>>>(out);
}

// round 13
// speedup vs baseline: 2.1005x; 1.0836x over previous
#include <cuda_runtime.h>
#include <cuda_fp16.h>
#include <math.h>
#include <stdint.h>

#define BB   2
#define TT   2048
#define DD   2048
#define NH   16
#define NKV  4
#define HDIM 128

// fp32 GEMM outputs (pre-rope)
__device__ float  g_q[BB*TT*NH*HDIM];
__device__ float  g_k[BB*TT*NKV*HDIM];
__device__ float  g_v[BB*TT*NKV*HDIM];
// fp16 operands
__device__ __half g_xh [BB*TT*DD];          // x fp16 [M][K]
__device__ __half g_wqh[NH*HDIM*DD];        // weights transposed [N][K]
__device__ __half g_wkh[NKV*HDIM*DD];
__device__ __half g_wvh[NKV*HDIM*DD];
__device__ __half g_woh[DD*DD];
__device__ __half g_qh [BB*TT*NH*HDIM];     // rope'd q (scaled) fp16
__device__ __half g_kh [BB*TT*NKV*HDIM];    // rope'd k fp16
__device__ __half g_vt [BB*NKV*HDIM*TT];    // v transposed [bkv][hd][t] fp16
__device__ __half g_oh [BB*TT*NH*HDIM];     // attention out fp16

__device__ __forceinline__ void mma_f16(float c[4],
                                        uint32_t a0, uint32_t a1, uint32_t a2, uint32_t a3,
                                        uint32_t b0, uint32_t b1) {
    asm volatile(
        "mma.sync.aligned.m16n8k16.row.col.f32.f16.f16.f32 "
        "{%0,%1,%2,%3}, {%4,%5,%6,%7}, {%8,%9}, {%0,%1,%2,%3};\n"
        : "+f"(c[0]), "+f"(c[1]), "+f"(c[2]), "+f"(c[3])
        : "r"(a0), "r"(a1), "r"(a2), "r"(a3), "r"(b0), "r"(b1));
}

__device__ __forceinline__ void cp_async16(uint32_t smem_addr, const void* gptr) {
    asm volatile("cp.async.cg.shared.global [%0], [%1], 16;\n"
                 :: "r"(smem_addr), "l"(gptr));
}
__device__ __forceinline__ void cp_async4(uint32_t smem_addr, const void* gptr) {
    asm volatile("cp.async.ca.shared.global [%0], [%1], 4;\n"
                 :: "r"(smem_addr), "l"(gptr));
}
__device__ __forceinline__ void cp_commit() {
    asm volatile("cp.async.commit_group;\n" ::: "memory");
}
template <int N>
__device__ __forceinline__ void cp_wait() {
    asm volatile("cp.async.wait_group %0;\n" :: "n"(N) : "memory");
}

// ---------------------------------------------------------------------------
// x -> fp16 elementwise
// ---------------------------------------------------------------------------
__global__ __launch_bounds__(256)
void cvt_x_kernel(const float4* __restrict__ src, __half2* __restrict__ dst, int n4) {
    int i = blockIdx.x * blockDim.x + threadIdx.x;
    if (i < n4) {
        float4 f = src[i];
        dst[2 * i]     = __floats2half2_rn(f.x, f.y);
        dst[2 * i + 1] = __floats2half2_rn(f.z, f.w);
    }
}

// transpose + cvt: src [K][N] fp32 -> dst [N][K] fp16
__global__ __launch_bounds__(256)
void cvt_t_kernel(const float* __restrict__ src, __half* __restrict__ dst,
                  int K, int N) {
    __shared__ float tile[32][33];
    const int n0 = blockIdx.x * 32;
    const int k0 = blockIdx.y * 32;
    const int tx = threadIdx.x & 31;
    const int ty = threadIdx.x >> 5;   // 0..7
    #pragma unroll
    for (int r = 0; r < 32; r += 8)
        tile[r + ty][tx] = src[(size_t)(k0 + r + ty) * N + n0 + tx];
    __syncthreads();
    #pragma unroll
    for (int r = 0; r < 32; r += 8)
        dst[(size_t)(n0 + r + ty) * K + k0 + tx] = __float2half_rn(tile[tx][r + ty]);
}

// V transpose + cvt: g_v fp32 [b*T][512] -> g_vt fp16 [(b*NKV+kv)][128][2048]
__global__ __launch_bounds__(256)
void vt_kernel() {
    __shared__ float tile[32][33];
    const int bk = blockIdx.z;
    const int b  = bk >> 2;
    const int kv = bk & 3;
    const int t0 = blockIdx.x * 32;
    const int d0 = blockIdx.y * 32;
    const int tx = threadIdx.x & 31;
    const int ty = threadIdx.x >> 5;
    #pragma unroll
    for (int r = 0; r < 32; r += 8)
        tile[r + ty][tx] =
            g_v[((size_t)b * TT + t0 + r + ty) * 512 + kv * 128 + d0 + tx];
    __syncthreads();
    __half* dst = g_vt + (size_t)bk * HDIM * TT;
    #pragma unroll
    for (int r = 0; r < 32; r += 8)
        dst[(size_t)(d0 + r + ty) * TT + t0 + tx] = __float2half_rn(tile[tx][r + ty]);
}

// ---------------------------------------------------------------------------
// fp16 mma.sync GEMM: 256 threads (8 warps), warp tile 64x32, BK=64 halves.
// Word pitch 36 (== 4 mod 32, conflict-free). 3-stage cp.async, one sync/iter.
// ---------------------------------------------------------------------------
#define GP   36
#define GASZ (128 * GP)
#define GSTG (2 * GASZ)
#define NSTG 3
#define GEMM_SMEM_BYTES (NSTG * GSTG * 4)

__device__ __forceinline__ void gemm_fill(const __half* __restrict__ A,
                                          const __half* __restrict__ Bt,
                                          int K, int k0,
                                          uint32_t aAddr, uint32_t bAddr, int tid) {
    #pragma unroll
    for (int v = 0; v < 4; v++) {
        int task = tid + 256 * v;     // 1024 chunks per operand
        int r  = task >> 3;
        int ch = task & 7;
        cp_async16(aAddr + (r * GP + ch * 4) * 4, A  + (size_t)r * K + k0 + ch * 8);
        cp_async16(bAddr + (r * GP + ch * 4) * 4, Bt + (size_t)r * K + k0 + ch * 8);
    }
}

__device__ __forceinline__ void gemm_body(
    const __half* __restrict__ A,    // [128+][K] K-major (row block applied)
    const __half* __restrict__ Bt,   // [128+][K] K-major (col block applied)
    float* __restrict__ C, int N, int K, uint32_t smem_base)
{
    const int tid  = threadIdx.x;
    const int wid  = tid >> 5;
    const int lane = tid & 31;
    const int g    = lane >> 2;
    const int tig  = lane & 3;

    const int warp_m = (wid & 1) * 64;
    const int warp_n = (wid >> 1) * 32;

    uint32_t* sm = (uint32_t*)__cvta_shared_to_generic(smem_base);

    float acc[4][4][4];
    #pragma unroll
    for (int i = 0; i < 4; i++)
        #pragma unroll
        for (int j = 0; j < 4; j++)
            #pragma unroll
            for (int c = 0; c < 4; c++) acc[i][j][c] = 0.0f;

    const int niter = K >> 6;   // BK = 64

    #pragma unroll
    for (int p = 0; p < NSTG - 1; p++) {
        uint32_t ab = smem_base + (p * GSTG) * 4;
        gemm_fill(A, Bt, K, p << 6, ab, ab + GASZ * 4, tid);
        cp_commit();
    }

    for (int i = 0; i < niter; i++) {
        cp_wait<NSTG - 2>();
        __syncthreads();

        const int ft = i + NSTG - 1;
        if (ft < niter) {
            const int fs = ft % NSTG;
            uint32_t ab = smem_base + (fs * GSTG) * 4;
            gemm_fill(A, Bt, K, ft << 6, ab, ab + GASZ * 4, tid);
        }
        cp_commit();

        const int cur = i % NSTG;
        const uint32_t* As = sm + cur * GSTG;
        const uint32_t* Bs = As + GASZ;

        #pragma unroll
        for (int ks = 0; ks < 4; ks++) {
            const int kk = ks * 8;
            uint32_t af[4][4];
            #pragma unroll
            for (int mt = 0; mt < 4; mt++) {
                int ar = warp_m + mt * 16 + g;
                af[mt][0] = As[ar * GP + kk + tig];
                af[mt][1] = As[(ar + 8) * GP + kk + tig];
                af[mt][2] = As[ar * GP + kk + tig + 4];
                af[mt][3] = As[(ar + 8) * GP + kk + tig + 4];
            }
            uint32_t bf[4][2];
            #pragma unroll
            for (int nt = 0; nt < 4; nt++) {
                int br = warp_n + nt * 8 + g;
                bf[nt][0] = Bs[br * GP + kk + tig];
                bf[nt][1] = Bs[br * GP + kk + tig + 4];
            }
            #pragma unroll
            for (int mt = 0; mt < 4; mt++)
                #pragma unroll
                for (int nt = 0; nt < 4; nt++)
                    mma_f16(acc[mt][nt], af[mt][0], af[mt][1], af[mt][2], af[mt][3],
                            bf[nt][0], bf[nt][1]);
        }
    }

    float* Cw = C + (size_t)warp_m * N + warp_n;
    #pragma unroll
    for (int mt = 0; mt < 4; mt++) {
        #pragma unroll
        for (int nt = 0; nt < 4; nt++) {
            int row = mt * 16 + g;
            int col = nt * 8 + 2 * tig;
            *(float2*)(Cw + (size_t)row * N + col) =
                make_float2(acc[mt][nt][0], acc[mt][nt][1]);
            *(float2*)(Cw + (size_t)(row + 8) * N + col) =
                make_float2(acc[mt][nt][2], acc[mt][nt][3]);
        }
    }
}

__global__ __launch_bounds__(256, 2)
void qkv_gemm_kernel(float* __restrict__ gq, float* __restrict__ gk,
                     float* __restrict__ gv) {
    extern __shared__ uint32_t smraw[];
    uint32_t smem_base = (uint32_t)__cvta_generic_to_shared(smraw);

    const int bx = blockIdx.x;
    const int by = blockIdx.y;

    const __half* Bsel;
    float* Csel;
    int Nsel, colb;
    if (bx < 16)      { Bsel = g_wqh; Csel = gq; Nsel = 2048; colb = bx * 128; }
    else if (bx < 20) { Bsel = g_wkh; Csel = gk; Nsel = 512;  colb = (bx - 16) * 128; }
    else              { Bsel = g_wvh; Csel = gv; Nsel = 512;  colb = (bx - 20) * 128; }

    gemm_body(g_xh + (size_t)by * 128 * DD,
              Bsel + (size_t)colb * DD,
              Csel + (size_t)by * 128 * Nsel + colb, Nsel, DD, smem_base);
}

__global__ __launch_bounds__(256, 2)
void wo_gemm_kernel(float* __restrict__ C) {
    extern __shared__ uint32_t smraw[];
    uint32_t smem_base = (uint32_t)__cvta_generic_to_shared(smraw);
    gemm_body(g_oh + (size_t)blockIdx.y * 128 * DD,
              g_woh + (size_t)blockIdx.x * 128 * DD,
              C + (size_t)blockIdx.y * 128 * DD + blockIdx.x * 128,
              DD, DD, smem_base);
}

// ---------------------------------------------------------------------------
// RoPE: g_q fp32 -> g_qh fp16 (scaled), g_k fp32 -> g_kh fp16
// ---------------------------------------------------------------------------
#define LOG2_THETA_OVER_HALF 0.20762050593046128f   // log2(10000)/64
#define ROPE_TOTQ (BB*TT*NH*64)
#define ROPE_TOTK (BB*TT*NKV*64)
#define ROPE_TOT  (ROPE_TOTQ + ROPE_TOTK)

__global__ __launch_bounds__(256)
void rope_kernel() {
    const float scale = 0.08838834764831845f;  // 1/sqrt(128)
    int idx = blockIdx.x * blockDim.x + threadIdx.x;
    if (idx < ROPE_TOTQ) {
        int d  = idx & 63;
        int h  = (idx >> 6) % NH;
        int bt = idx / (64 * NH);
        int t  = bt & (TT - 1);
        float inv = exp2f(-(float)d * LOG2_THETA_OVER_HALF);
        float ang = (float)t * inv;
        float s, c;
        sincosf(ang, &s, &c);
        const float* p = g_q + (size_t)bt * (NH * HDIM) + h * HDIM;
        __half* o = g_qh + (size_t)bt * (NH * HDIM) + h * HDIM;
        float x1 = p[d], x2 = p[d + 64];
        o[d]      = __float2half_rn((x1 * c - x2 * s) * scale);
        o[d + 64] = __float2half_rn((x2 * c + x1 * s) * scale);
    } else if (idx < ROPE_TOT) {
        int j  = idx - ROPE_TOTQ;
        int d  = j & 63;
        int h  = (j >> 6) % NKV;
        int bt = j / (64 * NKV);
        int t  = bt & (TT - 1);
        float inv = exp2f(-(float)d * LOG2_THETA_OVER_HALF);
        float ang = (float)t * inv;
        float s, c;
        sincosf(ang, &s, &c);
        const float* p = g_k + (size_t)bt * (NKV * HDIM) + h * HDIM;
        __half* o = g_kh + (size_t)bt * (NKV * HDIM) + h * HDIM;
        float x1 = p[d], x2 = p[d + 64];
        o[d]      = __float2half_rn(x1 * c - x2 * s);
        o[d + 64] = __float2half_rn(x2 * c + x1 * s);
    }
}

// ---------------------------------------------------------------------------
// fp16 flash attention, BM=128, BN=64, HD=128, 8 warps (16 rows each).
// K, V, mask ALL double-buffered; prefetch for kb+1 issued at the TOP of
// iteration kb (a full iteration of compute covers it); ONE sync per iter.
// Word pitches: Q/K 68, Vt 36, P 36 (all == 4 mod 32, conflict-free).
// smem words: Qs 8704 | Ks 2x4352=8704 | Vt 2x4608=9216 | Ps 4608 |
//             mask 2x64=128  -> 31360 words = 125440 B
// ---------------------------------------------------------------------------
#define QKP 68
#define VTP 36
#define PPW 36
#define QS_OFF   0
#define KS_OFF   8704
#define VS_OFF   17408
#define PS_OFF   26624
#define MASK_OFF 31232
#define ATTN_SMEM_BYTES (31360 * 4)

__global__ __launch_bounds__(256, 1)
void attn_mma_kernel(const int* __restrict__ mask, const int* __restrict__ causal_p) {
    extern __shared__ uint32_t sm[];
    const uint32_t smem_base = (uint32_t)__cvta_generic_to_shared(sm);
    uint32_t* Qs    = sm + QS_OFF;
    uint32_t* Ps    = sm + PS_OFF;
    int*      maskS = (int*)(sm + MASK_OFF);

    const int tid  = threadIdx.x;
    const int wid  = tid >> 5;
    const int lane = tid & 31;
    const int g    = lane >> 2;
    const int tig  = lane & 3;

    const int qb  = (gridDim.x - 1) - blockIdx.x;   // LPT
    const int h   = blockIdx.y;
    const int b   = blockIdx.z;
    const int kvh = h >> 2;
    const int causal = causal_p[0];

    const __half* qbase = g_qh + ((size_t)b * TT + qb * 128) * 2048 + h * HDIM;
    const __half* kbase = g_kh + (size_t)b * TT * 512 + kvh * HDIM;
    const __half* vtbase = g_vt + (size_t)(b * NKV + kvh) * HDIM * TT;
    const int*   mbase = mask + b * TT;

    // ---- prologue: Q whole, K0/Vt0/mask0 into buf0 ----
    #pragma unroll
    for (int it = 0; it < 8; it++) {
        int task = tid + 256 * it;            // 2048 chunks
        int r = task >> 4;
        int c = task & 15;
        cp_async16(smem_base + (QS_OFF + r * QKP + c * 4) * 4,
                   qbase + (size_t)r * 2048 + c * 8);
    }
    #pragma unroll
    for (int it = 0; it < 4; it++) {
        int task = tid + 256 * it;            // 1024 chunks
        int r = task >> 4;
        int c = task & 15;
        cp_async16(smem_base + (KS_OFF + r * QKP + c * 4) * 4,
                   kbase + (size_t)r * 512 + c * 8);
    }
    #pragma unroll
    for (int it = 0; it < 4; it++) {
        int task = tid + 256 * it;            // 1024 chunks (128 rows x 8)
        int r = task >> 3;
        int c = task & 7;
        cp_async16(smem_base + (VS_OFF + r * VTP + c * 4) * 4,
                   vtbase + (size_t)r * TT + c * 8);
    }
    if (tid < 64)
        cp_async4(smem_base + (MASK_OFF + tid) * 4, mbase + tid);
    cp_commit();

    const int r0  = 16 * wid + g;
    const int r1  = r0 + 8;
    const int qg0 = qb * 128 + r0;
    const int qg1 = qb * 128 + r1;

    float accO[16][4];
    #pragma unroll
    for (int nt = 0; nt < 16; nt++)
        #pragma unroll
        for (int c = 0; c < 4; c++) accO[nt][c] = 0.0f;

    float m0 = -1e30f, m1 = -1e30f, l0 = 0.0f, l1 = 0.0f;

    const int kbmax = causal ? (2 * qb + 1) : (TT / 64 - 1);

    for (int kb = 0; kb <= kbmax; kb++) {
        const int kr0 = kb * 64;
        const int cbuf = kb & 1;

        cp_wait<0>();          // buf cbuf (K,V,mask; +Q on kb=0) resident
        __syncthreads();       // all warps past iteration kb-1 (frees nbuf)

        // ---- prefetch kb+1 into alternate buffers (full iter to land) ----
        if (kb < kbmax) {
            const int nr0 = kr0 + 64;
            const int nbuf = (kb + 1) & 1;
            #pragma unroll
            for (int it = 0; it < 4; it++) {
                int task = tid + 256 * it;
                int r = task >> 4;
                int c = task & 15;
                cp_async16(smem_base + (KS_OFF + nbuf * 4352 + r * QKP + c * 4) * 4,
                           kbase + (size_t)(nr0 + r) * 512 + c * 8);
            }
            #pragma unroll
            for (int it = 0; it < 4; it++) {
                int task = tid + 256 * it;
                int r = task >> 3;
                int c = task & 7;
                cp_async16(smem_base + (VS_OFF + nbuf * 4608 + r * VTP + c * 4) * 4,
                           vtbase + (size_t)r * TT + nr0 + c * 8);
            }
            if (tid < 64)
                cp_async4(smem_base + (MASK_OFF + nbuf * 64 + tid) * 4,
                          mbase + nr0 + tid);
        }
        cp_commit();

        // ---- S = Q @ K^T : warp computes 16 x 64, k over 8 chunks of 16 ----
        const uint32_t* Kc = sm + KS_OFF + cbuf * 4352;
        float sacc[8][4];
        #pragma unroll
        for (int nt = 0; nt < 8; nt++)
            #pragma unroll
            for (int c = 0; c < 4; c++) sacc[nt][c] = 0.0f;

        #pragma unroll
        for (int ks = 0; ks < 8; ks++) {
            const uint32_t* qr = &Qs[r0 * QKP + ks * 8 + tig];
            uint32_t a0 = qr[0];
            uint32_t a2 = qr[4];
            uint32_t a1 = qr[8 * QKP];
            uint32_t a3 = qr[8 * QKP + 4];
            #pragma unroll
            for (int nt = 0; nt < 8; nt++) {
                const uint32_t* kr = &Kc[(8 * nt + g) * QKP + ks * 8 + tig];
                mma_f16(sacc[nt], a0, a1, a2, a3, kr[0], kr[4]);
            }
        }

        // ---- mask + warp-local row max ----
        const int* mcur = maskS + cbuf * 64;
        float lm0 = -1e30f, lm1 = -1e30f;
        #pragma unroll
        for (int nt = 0; nt < 8; nt++) {
            #pragma unroll
            for (int e = 0; e < 2; e++) {
                int c  = 8 * nt + 2 * tig + e;
                int kg = kr0 + c;
                bool mz = (mcur[c] == 0);
                if (mz || (causal && kg > qg0)) sacc[nt][e]     = -1e30f;
                if (mz || (causal && kg > qg1)) sacc[nt][e + 2] = -1e30f;
                lm0 = fmaxf(lm0, sacc[nt][e]);
                lm1 = fmaxf(lm1, sacc[nt][e + 2]);
            }
        }
        lm0 = fmaxf(lm0, __shfl_xor_sync(0xffffffffu, lm0, 1));
        lm0 = fmaxf(lm0, __shfl_xor_sync(0xffffffffu, lm0, 2));
        lm1 = fmaxf(lm1, __shfl_xor_sync(0xffffffffu, lm1, 1));
        lm1 = fmaxf(lm1, __shfl_xor_sync(0xffffffffu, lm1, 2));

        float mn0 = fmaxf(m0, lm0);
        float mn1 = fmaxf(m1, lm1);
        float esc0 = __expf(m0 - mn0);
        float esc1 = __expf(m1 - mn1);

        // ---- p = exp(s - m), row sums, pack half2 into Ps ----
        float ls0 = 0.0f, ls1 = 0.0f;
        #pragma unroll
        for (int nt = 0; nt < 8; nt++) {
            float p0 = __expf(sacc[nt][0] - mn0);
            float p1 = __expf(sacc[nt][1] - mn0);
            float p2 = __expf(sacc[nt][2] - mn1);
            float p3 = __expf(sacc[nt][3] - mn1);
            ls0 += p0 + p1;
            ls1 += p2 + p3;
            int cw = 4 * nt + tig;
            ((__half2*)Ps)[r0 * PPW + cw] = __floats2half2_rn(p0, p1);
            ((__half2*)Ps)[r1 * PPW + cw] = __floats2half2_rn(p2, p3);
        }
        ls0 += __shfl_xor_sync(0xffffffffu, ls0, 1);
        ls0 += __shfl_xor_sync(0xffffffffu, ls0, 2);
        ls1 += __shfl_xor_sync(0xffffffffu, ls1, 1);
        ls1 += __shfl_xor_sync(0xffffffffu, ls1, 2);

        l0 = l0 * esc0 + ls0;
        l1 = l1 * esc1 + ls1;
        m0 = mn0;
        m1 = mn1;

        #pragma unroll
        for (int nt = 0; nt < 16; nt++) {
            accO[nt][0] *= esc0; accO[nt][1] *= esc0;
            accO[nt][2] *= esc1; accO[nt][3] *= esc1;
        }
        __syncwarp();

        // ---- O += P @ V : k = 64 keys over 4 chunks of 16 ----
        const uint32_t* Vc = sm + VS_OFF + cbuf * 4608;
        #pragma unroll
        for (int ks = 0; ks < 4; ks++) {
            const uint32_t* pr = &Ps[r0 * PPW + ks * 8 + tig];
            uint32_t a0 = pr[0];
            uint32_t a2 = pr[4];
            uint32_t a1 = pr[8 * PPW];
            uint32_t a3 = pr[8 * PPW + 4];
            #pragma unroll
            for (int nt = 0; nt < 16; nt++) {
                const uint32_t* vr = &Vc[(8 * nt + g) * VTP + ks * 8 + tig];
                mma_f16(accO[nt], a0, a1, a2, a3, vr[0], vr[4]);
            }
        }
    }

    // ---- epilogue: normalize, write fp16 ----
    float invl0 = 1.0f / l0;
    float invl1 = 1.0f / l1;
    __half2* oh0 = (__half2*)(g_oh + ((size_t)b * TT + qb * 128 + r0) * 2048 + h * HDIM);
    __half2* oh1 = (__half2*)(g_oh + ((size_t)b * TT + qb * 128 + r1) * 2048 + h * HDIM);
    #pragma unroll
    for (int nt = 0; nt < 16; nt++) {
        oh0[4 * nt + tig] = __floats2half2_rn(accO[nt][0] * invl0, accO[nt][1] * invl0);
        oh1[4 * nt + tig] = __floats2half2_rn(accO[nt][2] * invl1, accO[nt][3] * invl1);
    }
}

// ---------------------------------------------------------------------------
extern "C" void kernel_launch(void* const* d_in, const int* in_sizes, int n_in,
                              void* d_out, int out_size) {
    const float* x      = (const float*)d_in[0];
    const int*   mask   = (const int*)d_in[1];
    const int*   causal = (const int*)d_in[2];
    const float* wq     = (const float*)d_in[3];
    const float* wk     = (const float*)d_in[4];
    const float* wv     = (const float*)d_in[5];
    const float* wo     = (const float*)d_in[6];
    float* out = (float*)d_out;

    float *gq, *gk, *gv;
    __half *xh, *wqh, *wkh, *wvh, *woh;
    cudaGetSymbolAddress((void**)&gq,  g_q);
    cudaGetSymbolAddress((void**)&gk,  g_k);
    cudaGetSymbolAddress((void**)&gv,  g_v);
    cudaGetSymbolAddress((void**)&xh,  g_xh);
    cudaGetSymbolAddress((void**)&wqh, g_wqh);
    cudaGetSymbolAddress((void**)&wkh, g_wkh);
    cudaGetSymbolAddress((void**)&wvh, g_wvh);
    cudaGetSymbolAddress((void**)&woh, g_woh);

    const int M = BB * TT;  // 4096

    cudaFuncSetAttribute(qkv_gemm_kernel, cudaFuncAttributeMaxDynamicSharedMemorySize,
                         GEMM_SMEM_BYTES);
    cudaFuncSetAttribute(wo_gemm_kernel, cudaFuncAttributeMaxDynamicSharedMemorySize,
                         GEMM_SMEM_BYTES);
    cudaFuncSetAttribute(attn_mma_kernel, cudaFuncAttributeMaxDynamicSharedMemorySize,
                         ATTN_SMEM_BYTES);

    // x -> fp16; weights -> transposed fp16
    {
        int n4 = (M * DD) / 4;
        cvt_x_kernel<<<(n4 + 255) / 256, 256>>>((const float4*)x, (__half2*)xh, n4);
        cvt_t_kernel<<<dim3(2048 / 32, 2048 / 32), 256>>>(wq, wqh, 2048, 2048);
        cvt_t_kernel<<<dim3(512 / 32,  2048 / 32), 256>>>(wk, wkh, 2048, 512);
        cvt_t_kernel<<<dim3(512 / 32,  2048 / 32), 256>>>(wv, wvh, 2048, 512);
        cvt_t_kernel<<<dim3(2048 / 32, 2048 / 32), 256>>>(wo, woh, 2048, 2048);
    }

    // Fused QKV projection (fp16 in, fp32 out)
    qkv_gemm_kernel<<<dim3(24, M / 128), 256, GEMM_SMEM_BYTES>>>(gq, gk, gv);

    // RoPE -> fp16 q (scaled), k
    rope_kernel<<<(ROPE_TOT + 255) / 256, 256>>>();

    // V transpose + cvt -> g_vt fp16
    vt_kernel<<<dim3(TT / 32, HDIM / 32, BB * NKV), 256>>>();

    // Attention (fp16 mma, fully double-buffered, 1 sync/iter)
    attn_mma_kernel<<<dim3(TT / 128, NH, BB), 256, ATTN_SMEM_BYTES>>>(mask, causal);

    // Output projection (fp16 in, fp32 out)
    wo_gemm_kernel<<<dim3(DD / 128, M / 128), 256, GEMM_SMEM_BYTES>>>(out);
}

// round 15
// speedup vs baseline: 2.1924x; 1.0437x over previous
#include <cuda_runtime.h>
#include <cuda_fp16.h>
#include <math.h>
#include <stdint.h>

#define BB   2
#define TT   2048
#define DD   2048
#define NH   16
#define NKV  4
#define HDIM 128

// fp32 GEMM outputs (pre-rope)
__device__ float  g_q[BB*TT*NH*HDIM];
__device__ float  g_k[BB*TT*NKV*HDIM];
__device__ float  g_v[BB*TT*NKV*HDIM];
// fp16 operands
__device__ __half g_xh [BB*TT*DD];          // x fp16 [M][K]
__device__ __half g_wqh[NH*HDIM*DD];        // weights transposed [N][K]
__device__ __half g_wkh[NKV*HDIM*DD];
__device__ __half g_wvh[NKV*HDIM*DD];
__device__ __half g_woh[DD*DD];
__device__ __half g_qh [BB*TT*NH*HDIM];     // rope'd q (scaled) fp16
__device__ __half g_kh [BB*TT*NKV*HDIM];    // rope'd k fp16
__device__ __half g_vt [BB*NKV*HDIM*TT];    // v transposed [bkv][hd][t] fp16
__device__ __half g_oh [BB*TT*NH*HDIM];     // attention out fp16

__device__ __forceinline__ uint32_t h2_as_u32(__half2 h) {
    return *reinterpret_cast<uint32_t*>(&h);
}

__device__ __forceinline__ void mma_f16(float c[4],
                                        uint32_t a0, uint32_t a1, uint32_t a2, uint32_t a3,
                                        uint32_t b0, uint32_t b1) {
    asm volatile(
        "mma.sync.aligned.m16n8k16.row.col.f32.f16.f16.f32 "
        "{%0,%1,%2,%3}, {%4,%5,%6,%7}, {%8,%9}, {%0,%1,%2,%3};\n"
        : "+f"(c[0]), "+f"(c[1]), "+f"(c[2]), "+f"(c[3])
        : "r"(a0), "r"(a1), "r"(a2), "r"(a3), "r"(b0), "r"(b1));
}

__device__ __forceinline__ void cp_async16(uint32_t smem_addr, const void* gptr) {
    asm volatile("cp.async.cg.shared.global [%0], [%1], 16;\n"
                 :: "r"(smem_addr), "l"(gptr));
}
__device__ __forceinline__ void cp_async4(uint32_t smem_addr, const void* gptr) {
    asm volatile("cp.async.ca.shared.global [%0], [%1], 4;\n"
                 :: "r"(smem_addr), "l"(gptr));
}
__device__ __forceinline__ void cp_commit() {
    asm volatile("cp.async.commit_group;\n" ::: "memory");
}
template <int N>
__device__ __forceinline__ void cp_wait() {
    asm volatile("cp.async.wait_group %0;\n" :: "n"(N) : "memory");
}

// ---------------------------------------------------------------------------
// x -> fp16 elementwise
// ---------------------------------------------------------------------------
__global__ __launch_bounds__(256)
void cvt_x_kernel(const float4* __restrict__ src, __half2* __restrict__ dst, int n4) {
    int i = blockIdx.x * blockDim.x + threadIdx.x;
    if (i < n4) {
        float4 f = src[i];
        dst[2 * i]     = __floats2half2_rn(f.x, f.y);
        dst[2 * i + 1] = __floats2half2_rn(f.z, f.w);
    }
}

// All four weight transposes in ONE launch.
__global__ __launch_bounds__(256)
void cvt_w_kernel(const float* __restrict__ wq, const float* __restrict__ wk,
                  const float* __restrict__ wv, const float* __restrict__ wo) {
    __shared__ float tile[32][33];
    int id = blockIdx.x;
    const float* src; __half* dst; int N, n0, k0;
    if (id < 4096)      { src = wq; dst = g_wqh; N = 2048; int j = id;        n0 = (j & 63) * 32; k0 = (j >> 6) * 32; }
    else if (id < 5120) { src = wk; dst = g_wkh; N = 512;  int j = id - 4096; n0 = (j & 15) * 32; k0 = (j >> 4) * 32; }
    else if (id < 6144) { src = wv; dst = g_wvh; N = 512;  int j = id - 5120; n0 = (j & 15) * 32; k0 = (j >> 4) * 32; }
    else                { src = wo; dst = g_woh; N = 2048; int j = id - 6144; n0 = (j & 63) * 32; k0 = (j >> 6) * 32; }
    const int K = 2048;
    const int tx = threadIdx.x & 31;
    const int ty = threadIdx.x >> 5;   // 0..7
    #pragma unroll
    for (int r = 0; r < 32; r += 8)
        tile[r + ty][tx] = src[(size_t)(k0 + r + ty) * N + n0 + tx];
    __syncthreads();
    #pragma unroll
    for (int r = 0; r < 32; r += 8)
        dst[(size_t)(n0 + r + ty) * K + k0 + tx] = __float2half_rn(tile[tx][r + ty]);
}

// V transpose + cvt: g_v fp32 [b*T][512] -> g_vt fp16 [(b*NKV+kv)][128][2048]
__global__ __launch_bounds__(256)
void vt_kernel() {
    __shared__ float tile[32][33];
    const int bk = blockIdx.z;
    const int b  = bk >> 2;
    const int kv = bk & 3;
    const int t0 = blockIdx.x * 32;
    const int d0 = blockIdx.y * 32;
    const int tx = threadIdx.x & 31;
    const int ty = threadIdx.x >> 5;
    #pragma unroll
    for (int r = 0; r < 32; r += 8)
        tile[r + ty][tx] =
            g_v[((size_t)b * TT + t0 + r + ty) * 512 + kv * 128 + d0 + tx];
    __syncthreads();
    __half* dst = g_vt + (size_t)bk * HDIM * TT;
    #pragma unroll
    for (int r = 0; r < 32; r += 8)
        dst[(size_t)(d0 + r + ty) * TT + t0 + tx] = __float2half_rn(tile[tx][r + ty]);
}

// ---------------------------------------------------------------------------
// fp16 mma.sync GEMM: 256 threads (8 warps), warp tile 64x32, BK=64 halves.
// Word pitch 36 (== 4 mod 32, conflict-free). 3-stage cp.async, one sync/iter.
// ---------------------------------------------------------------------------
#define GP   36
#define GASZ (128 * GP)
#define GSTG (2 * GASZ)
#define NSTG 3
#define GEMM_SMEM_BYTES (NSTG * GSTG * 4)

__device__ __forceinline__ void gemm_fill(const __half* __restrict__ A,
                                          const __half* __restrict__ Bt,
                                          int K, int k0,
                                          uint32_t aAddr, uint32_t bAddr, int tid) {
    #pragma unroll
    for (int v = 0; v < 4; v++) {
        int task = tid + 256 * v;     // 1024 chunks per operand
        int r  = task >> 3;
        int ch = task & 7;
        cp_async16(aAddr + (r * GP + ch * 4) * 4, A  + (size_t)r * K + k0 + ch * 8);
        cp_async16(bAddr + (r * GP + ch * 4) * 4, Bt + (size_t)r * K + k0 + ch * 8);
    }
}

__device__ __forceinline__ void gemm_body(
    const __half* __restrict__ A,    // [128+][K] K-major (row block applied)
    const __half* __restrict__ Bt,   // [128+][K] K-major (col block applied)
    float* __restrict__ C, int N, int K, uint32_t smem_base)
{
    const int tid  = threadIdx.x;
    const int wid  = tid >> 5;
    const int lane = tid & 31;
    const int g    = lane >> 2;
    const int tig  = lane & 3;

    const int warp_m = (wid & 1) * 64;
    const int warp_n = (wid >> 1) * 32;

    uint32_t* sm = (uint32_t*)__cvta_shared_to_generic(smem_base);

    float acc[4][4][4];
    #pragma unroll
    for (int i = 0; i < 4; i++)
        #pragma unroll
        for (int j = 0; j < 4; j++)
            #pragma unroll
            for (int c = 0; c < 4; c++) acc[i][j][c] = 0.0f;

    const int niter = K >> 6;   // BK = 64

    #pragma unroll
    for (int p = 0; p < NSTG - 1; p++) {
        uint32_t ab = smem_base + (p * GSTG) * 4;
        gemm_fill(A, Bt, K, p << 6, ab, ab + GASZ * 4, tid);
        cp_commit();
    }

    for (int i = 0; i < niter; i++) {
        cp_wait<NSTG - 2>();
        __syncthreads();

        const int ft = i + NSTG - 1;
        if (ft < niter) {
            const int fs = ft % NSTG;
            uint32_t ab = smem_base + (fs * GSTG) * 4;
            gemm_fill(A, Bt, K, ft << 6, ab, ab + GASZ * 4, tid);
        }
        cp_commit();

        const int cur = i % NSTG;
        const uint32_t* As = sm + cur * GSTG;
        const uint32_t* Bs = As + GASZ;

        #pragma unroll
        for (int ks = 0; ks < 4; ks++) {
            const int kk = ks * 8;
            uint32_t af[4][4];
            #pragma unroll
            for (int mt = 0; mt < 4; mt++) {
                int ar = warp_m + mt * 16 + g;
                af[mt][0] = As[ar * GP + kk + tig];
                af[mt][1] = As[(ar + 8) * GP + kk + tig];
                af[mt][2] = As[ar * GP + kk + tig + 4];
                af[mt][3] = As[(ar + 8) * GP + kk + tig + 4];
            }
            uint32_t bf[4][2];
            #pragma unroll
            for (int nt = 0; nt < 4; nt++) {
                int br = warp_n + nt * 8 + g;
                bf[nt][0] = Bs[br * GP + kk + tig];
                bf[nt][1] = Bs[br * GP + kk + tig + 4];
            }
            #pragma unroll
            for (int mt = 0; mt < 4; mt++)
                #pragma unroll
                for (int nt = 0; nt < 4; nt++)
                    mma_f16(acc[mt][nt], af[mt][0], af[mt][1], af[mt][2], af[mt][3],
                            bf[nt][0], bf[nt][1]);
        }
    }

    float* Cw = C + (size_t)warp_m * N + warp_n;
    #pragma unroll
    for (int mt = 0; mt < 4; mt++) {
        #pragma unroll
        for (int nt = 0; nt < 4; nt++) {
            int row = mt * 16 + g;
            int col = nt * 8 + 2 * tig;
            *(float2*)(Cw + (size_t)row * N + col) =
                make_float2(acc[mt][nt][0], acc[mt][nt][1]);
            *(float2*)(Cw + (size_t)(row + 8) * N + col) =
                make_float2(acc[mt][nt][2], acc[mt][nt][3]);
        }
    }
}

__global__ __launch_bounds__(256, 2)
void qkv_gemm_kernel(float* __restrict__ gq, float* __restrict__ gk,
                     float* __restrict__ gv) {
    extern __shared__ uint32_t smraw[];
    uint32_t smem_base = (uint32_t)__cvta_generic_to_shared(smraw);

    const int bx = blockIdx.x;
    const int by = blockIdx.y;

    const __half* Bsel;
    float* Csel;
    int Nsel, colb;
    if (bx < 16)      { Bsel = g_wqh; Csel = gq; Nsel = 2048; colb = bx * 128; }
    else if (bx < 20) { Bsel = g_wkh; Csel = gk; Nsel = 512;  colb = (bx - 16) * 128; }
    else              { Bsel = g_wvh; Csel = gv; Nsel = 512;  colb = (bx - 20) * 128; }

    gemm_body(g_xh + (size_t)by * 128 * DD,
              Bsel + (size_t)colb * DD,
              Csel + (size_t)by * 128 * Nsel + colb, Nsel, DD, smem_base);
}

__global__ __launch_bounds__(256, 2)
void wo_gemm_kernel(float* __restrict__ C) {
    extern __shared__ uint32_t smraw[];
    uint32_t smem_base = (uint32_t)__cvta_generic_to_shared(smraw);
    gemm_body(g_oh + (size_t)blockIdx.y * 128 * DD,
              g_woh + (size_t)blockIdx.x * 128 * DD,
              C + (size_t)blockIdx.y * 128 * DD + blockIdx.x * 128,
              DD, DD, smem_base);
}

// ---------------------------------------------------------------------------
// RoPE: g_q fp32 -> g_qh fp16 (scaled), g_k fp32 -> g_kh fp16
// ---------------------------------------------------------------------------
#define LOG2_THETA_OVER_HALF 0.20762050593046128f   // log2(10000)/64
#define ROPE_TOTQ (BB*TT*NH*64)
#define ROPE_TOTK (BB*TT*NKV*64)
#define ROPE_TOT  (ROPE_TOTQ + ROPE_TOTK)

__global__ __launch_bounds__(256)
void rope_kernel() {
    const float scale = 0.08838834764831845f;  // 1/sqrt(128)
    int idx = blockIdx.x * blockDim.x + threadIdx.x;
    if (idx < ROPE_TOTQ) {
        int d  = idx & 63;
        int h  = (idx >> 6) % NH;
        int bt = idx / (64 * NH);
        int t  = bt & (TT - 1);
        float inv = exp2f(-(float)d * LOG2_THETA_OVER_HALF);
        float ang = (float)t * inv;
        float s, c;
        sincosf(ang, &s, &c);
        const float* p = g_q + (size_t)bt * (NH * HDIM) + h * HDIM;
        __half* o = g_qh + (size_t)bt * (NH * HDIM) + h * HDIM;
        float x1 = p[d], x2 = p[d + 64];
        o[d]      = __float2half_rn((x1 * c - x2 * s) * scale);
        o[d + 64] = __float2half_rn((x2 * c + x1 * s) * scale);
    } else if (idx < ROPE_TOT) {
        int j  = idx - ROPE_TOTQ;
        int d  = j & 63;
        int h  = (j >> 6) % NKV;
        int bt = j / (64 * NKV);
        int t  = bt & (TT - 1);
        float inv = exp2f(-(float)d * LOG2_THETA_OVER_HALF);
        float ang = (float)t * inv;
        float s, c;
        sincosf(ang, &s, &c);
        const float* p = g_k + (size_t)bt * (NKV * HDIM) + h * HDIM;
        __half* o = g_kh + (size_t)bt * (NKV * HDIM) + h * HDIM;
        float x1 = p[d], x2 = p[d + 64];
        o[d]      = __float2half_rn(x1 * c - x2 * s);
        o[d + 64] = __float2half_rn(x2 * c + x1 * s);
    }
}

// ---------------------------------------------------------------------------
// fp16 flash attention, BM=128, BN=64, HD=128, 8 warps (16 rows each).
// K/V/mask double-buffered, prefetch at top of iteration, ONE sync per iter.
// Q fragments hoisted to registers (loaded once at kb=0).
// P kept ENTIRELY in registers (sacc -> half2 fragments, no smem staging).
// smem words: Qs 8704 | Ks 2x4352=8704 | Vt 2x4608=9216 | mask 2x64=128
//   -> 26752 words = 107008 B
// ---------------------------------------------------------------------------
#define QKP 68
#define VTP 36
#define QS_OFF   0
#define KS_OFF   8704
#define VS_OFF   17408
#define MASK_OFF 26624
#define ATTN_SMEM_BYTES (26752 * 4)

__global__ __launch_bounds__(256, 1)
void attn_mma_kernel(const int* __restrict__ mask, const int* __restrict__ causal_p) {
    extern __shared__ uint32_t sm[];
    const uint32_t smem_base = (uint32_t)__cvta_generic_to_shared(sm);
    uint32_t* Qs    = sm + QS_OFF;
    int*      maskS = (int*)(sm + MASK_OFF);

    const int tid  = threadIdx.x;
    const int wid  = tid >> 5;
    const int lane = tid & 31;
    const int g    = lane >> 2;
    const int tig  = lane & 3;

    const int qb  = (gridDim.x - 1) - blockIdx.x;   // LPT
    const int h   = blockIdx.y;
    const int b   = blockIdx.z;
    const int kvh = h >> 2;
    const int causal = causal_p[0];

    const __half* qbase = g_qh + ((size_t)b * TT + qb * 128) * 2048 + h * HDIM;
    const __half* kbase = g_kh + (size_t)b * TT * 512 + kvh * HDIM;
    const __half* vtbase = g_vt + (size_t)(b * NKV + kvh) * HDIM * TT;
    const int*   mbase = mask + b * TT;

    // ---- prologue: Q whole, K0/Vt0/mask0 into buf0 ----
    #pragma unroll
    for (int it = 0; it < 8; it++) {
        int task = tid + 256 * it;            // 2048 chunks
        int r = task >> 4;
        int c = task & 15;
        cp_async16(smem_base + (QS_OFF + r * QKP + c * 4) * 4,
                   qbase + (size_t)r * 2048 + c * 8);
    }
    #pragma unroll
    for (int it = 0; it < 4; it++) {
        int task = tid + 256 * it;            // 1024 chunks
        int r = task >> 4;
        int c = task & 15;
        cp_async16(smem_base + (KS_OFF + r * QKP + c * 4) * 4,
                   kbase + (size_t)r * 512 + c * 8);
    }
    #pragma unroll
    for (int it = 0; it < 4; it++) {
        int task = tid + 256 * it;            // 1024 chunks (128 rows x 8)
        int r = task >> 3;
        int c = task & 7;
        cp_async16(smem_base + (VS_OFF + r * VTP + c * 4) * 4,
                   vtbase + (size_t)r * TT + c * 8);
    }
    if (tid < 64)
        cp_async4(smem_base + (MASK_OFF + tid) * 4, mbase + tid);
    cp_commit();

    const int r0  = 16 * wid + g;
    const int r1  = r0 + 8;
    const int qg0 = qb * 128 + r0;
    const int qg1 = qb * 128 + r1;

    float accO[16][4];
    #pragma unroll
    for (int nt = 0; nt < 16; nt++)
        #pragma unroll
        for (int c = 0; c < 4; c++) accO[nt][c] = 0.0f;

    float m0 = -1e30f, m1 = -1e30f, l0 = 0.0f, l1 = 0.0f;

    uint32_t qa[8][4];   // hoisted Q fragments (loaded at kb=0)

    const int kbmax = causal ? (2 * qb + 1) : (TT / 64 - 1);

    for (int kb = 0; kb <= kbmax; kb++) {
        const int kr0 = kb * 64;
        const int cbuf = kb & 1;

        cp_wait<0>();          // buf cbuf (K,V,mask; +Q on kb=0) resident
        __syncthreads();       // all warps past iteration kb-1 (frees nbuf)

        if (kb == 0) {
            #pragma unroll
            for (int ks = 0; ks < 8; ks++) {
                const uint32_t* qr = &Qs[r0 * QKP + ks * 8 + tig];
                qa[ks][0] = qr[0];
                qa[ks][2] = qr[4];
                qa[ks][1] = qr[8 * QKP];
                qa[ks][3] = qr[8 * QKP + 4];
            }
        }

        // ---- prefetch kb+1 into alternate buffers (full iter to land) ----
        if (kb < kbmax) {
            const int nr0 = kr0 + 64;
            const int nbuf = (kb + 1) & 1;
            #pragma unroll
            for (int it = 0; it < 4; it++) {
                int task = tid + 256 * it;
                int r = task >> 4;
                int c = task & 15;
                cp_async16(smem_base + (KS_OFF + nbuf * 4352 + r * QKP + c * 4) * 4,
                           kbase + (size_t)(nr0 + r) * 512 + c * 8);
            }
            #pragma unroll
            for (int it = 0; it < 4; it++) {
                int task = tid + 256 * it;
                int r = task >> 3;
                int c = task & 7;
                cp_async16(smem_base + (VS_OFF + nbuf * 4608 + r * VTP + c * 4) * 4,
                           vtbase + (size_t)r * TT + nr0 + c * 8);
            }
            if (tid < 64)
                cp_async4(smem_base + (MASK_OFF + nbuf * 64 + tid) * 4,
                          mbase + nr0 + tid);
        }
        cp_commit();

        // ---- S = Q @ K^T : warp computes 16 x 64, k over 8 chunks of 16 ----
        const uint32_t* Kc = sm + KS_OFF + cbuf * 4352;
        float sacc[8][4];
        #pragma unroll
        for (int nt = 0; nt < 8; nt++)
            #pragma unroll
            for (int c = 0; c < 4; c++) sacc[nt][c] = 0.0f;

        #pragma unroll
        for (int ks = 0; ks < 8; ks++) {
            #pragma unroll
            for (int nt = 0; nt < 8; nt++) {
                const uint32_t* kr = &Kc[(8 * nt + g) * QKP + ks * 8 + tig];
                mma_f16(sacc[nt], qa[ks][0], qa[ks][1], qa[ks][2], qa[ks][3],
                        kr[0], kr[4]);
            }
        }

        // ---- mask + warp-local row max ----
        const int* mcur = maskS + cbuf * 64;
        float lm0 = -1e30f, lm1 = -1e30f;
        #pragma unroll
        for (int nt = 0; nt < 8; nt++) {
            #pragma unroll
            for (int e = 0; e < 2; e++) {
                int c  = 8 * nt + 2 * tig + e;
                int kg = kr0 + c;
                bool mz = (mcur[c] == 0);
                if (mz || (causal && kg > qg0)) sacc[nt][e]     = -1e30f;
                if (mz || (causal && kg > qg1)) sacc[nt][e + 2] = -1e30f;
                lm0 = fmaxf(lm0, sacc[nt][e]);
                lm1 = fmaxf(lm1, sacc[nt][e + 2]);
            }
        }
        lm0 = fmaxf(lm0, __shfl_xor_sync(0xffffffffu, lm0, 1));
        lm0 = fmaxf(lm0, __shfl_xor_sync(0xffffffffu, lm0, 2));
        lm1 = fmaxf(lm1, __shfl_xor_sync(0xffffffffu, lm1, 1));
        lm1 = fmaxf(lm1, __shfl_xor_sync(0xffffffffu, lm1, 2));

        float mn0 = fmaxf(m0, lm0);
        float mn1 = fmaxf(m1, lm1);
        float esc0 = __expf(m0 - mn0);
        float esc1 = __expf(m1 - mn1);

        // ---- p = exp(s - m), row sums, fragments stay in registers ----
        float ls0 = 0.0f, ls1 = 0.0f;
        uint32_t pw0[8], pw1[8];
        #pragma unroll
        for (int nt = 0; nt < 8; nt++) {
            float p0 = __expf(sacc[nt][0] - mn0);
            float p1 = __expf(sacc[nt][1] - mn0);
            float p2 = __expf(sacc[nt][2] - mn1);
            float p3 = __expf(sacc[nt][3] - mn1);
            ls0 += p0 + p1;
            ls1 += p2 + p3;
            pw0[nt] = h2_as_u32(__floats2half2_rn(p0, p1));
            pw1[nt] = h2_as_u32(__floats2half2_rn(p2, p3));
        }
        ls0 += __shfl_xor_sync(0xffffffffu, ls0, 1);
        ls0 += __shfl_xor_sync(0xffffffffu, ls0, 2);
        ls1 += __shfl_xor_sync(0xffffffffu, ls1, 1);
        ls1 += __shfl_xor_sync(0xffffffffu, ls1, 2);

        l0 = l0 * esc0 + ls0;
        l1 = l1 * esc1 + ls1;
        m0 = mn0;
        m1 = mn1;

        #pragma unroll
        for (int nt = 0; nt < 16; nt++) {
            accO[nt][0] *= esc0; accO[nt][1] *= esc0;
            accO[nt][2] *= esc1; accO[nt][3] *= esc1;
        }

        // ---- O += P @ V : k = 64 keys over 4 chunks of 16 (P from regs) ----
        const uint32_t* Vc = sm + VS_OFF + cbuf * 4608;
        #pragma unroll
        for (int ks = 0; ks < 4; ks++) {
            uint32_t a0 = pw0[2 * ks];
            uint32_t a1 = pw1[2 * ks];
            uint32_t a2 = pw0[2 * ks + 1];
            uint32_t a3 = pw1[2 * ks + 1];
            #pragma unroll
            for (int nt = 0; nt < 16; nt++) {
                const uint32_t* vr = &Vc[(8 * nt + g) * VTP + ks * 8 + tig];
                mma_f16(accO[nt], a0, a1, a2, a3, vr[0], vr[4]);
            }
        }
    }

    // ---- epilogue: normalize, write fp16 ----
    float invl0 = 1.0f / l0;
    float invl1 = 1.0f / l1;
    __half2* oh0 = (__half2*)(g_oh + ((size_t)b * TT + qb * 128 + r0) * 2048 + h * HDIM);
    __half2* oh1 = (__half2*)(g_oh + ((size_t)b * TT + qb * 128 + r1) * 2048 + h * HDIM);
    #pragma unroll
    for (int nt = 0; nt < 16; nt++) {
        oh0[4 * nt + tig] = __floats2half2_rn(accO[nt][0] * invl0, accO[nt][1] * invl0);
        oh1[4 * nt + tig] = __floats2half2_rn(accO[nt][2] * invl1, accO[nt][3] * invl1);
    }
}

// ---------------------------------------------------------------------------
extern "C" void kernel_launch(void* const* d_in, const int* in_sizes, int n_in,
                              void* d_out, int out_size) {
    const float* x      = (const float*)d_in[0];
    const int*   mask   = (const int*)d_in[1];
    const int*   causal = (const int*)d_in[2];
    const float* wq     = (const float*)d_in[3];
    const float* wk     = (const float*)d_in[4];
    const float* wv     = (const float*)d_in[5];
    const float* wo     = (const float*)d_in[6];
    float* out = (float*)d_out;

    float *gq, *gk, *gv;
    __half *xh;
    cudaGetSymbolAddress((void**)&gq,  g_q);
    cudaGetSymbolAddress((void**)&gk,  g_k);
    cudaGetSymbolAddress((void**)&gv,  g_v);
    cudaGetSymbolAddress((void**)&xh,  g_xh);

    const int M = BB * TT;  // 4096

    cudaFuncSetAttribute(qkv_gemm_kernel, cudaFuncAttributeMaxDynamicSharedMemorySize,
                         GEMM_SMEM_BYTES);
    cudaFuncSetAttribute(wo_gemm_kernel, cudaFuncAttributeMaxDynamicSharedMemorySize,
                         GEMM_SMEM_BYTES);
    cudaFuncSetAttribute(attn_mma_kernel, cudaFuncAttributeMaxDynamicSharedMemorySize,
                         ATTN_SMEM_BYTES);

    // x -> fp16; weights -> transposed fp16 (one launch)
    {
        int n4 = (M * DD) / 4;
        cvt_x_kernel<<<(n4 + 255) / 256, 256>>>((const float4*)x, (__half2*)xh, n4);
        cvt_w_kernel<<<10240, 256>>>(wq, wk, wv, wo);
    }

    // Fused QKV projection (fp16 in, fp32 out)
    qkv_gemm_kernel<<<dim3(24, M / 128), 256, GEMM_SMEM_BYTES>>>(gq, gk, gv);

    // RoPE -> fp16 q (scaled), k
    rope_kernel<<<(ROPE_TOT + 255) / 256, 256>>>();

    // V transpose + cvt -> g_vt fp16
    vt_kernel<<<dim3(TT / 32, HDIM / 32, BB * NKV), 256>>>();

    // Attention (fp16 mma, register-resident P, hoisted Q)
    attn_mma_kernel<<<dim3(TT / 128, NH, BB), 256, ATTN_SMEM_BYTES>>>(mask, causal);

    // Output projection (fp16 in, fp32 out)
    wo_gemm_kernel<<<dim3(DD / 128, M / 128), 256, GEMM_SMEM_BYTES>>>(out);
}

// round 16
// speedup vs baseline: 2.2303x; 1.0173x over previous
#include <cuda_runtime.h>
#include <cuda_fp16.h>
#include <math.h>
#include <stdint.h>

#define BB   2
#define TT   2048
#define DD   2048
#define NH   16
#define NKV  4
#define HDIM 128

// fp16 operands
__device__ __half g_xh [BB*TT*DD];          // x fp16 [M][K]
__device__ __half g_wqh[NH*HDIM*DD];        // weights transposed [N][K]
__device__ __half g_wkh[NKV*HDIM*DD];
__device__ __half g_wvh[NKV*HDIM*DD];
__device__ __half g_woh[DD*DD];
__device__ __half g_qh [BB*TT*NH*HDIM];     // rope'd q (scaled) fp16
__device__ __half g_kh [BB*TT*NKV*HDIM];    // rope'd k fp16
__device__ __half g_vt [BB*NKV*HDIM*TT];    // v transposed [bkv][hd][t] fp16
__device__ __half g_oh [BB*TT*NH*HDIM];     // attention out fp16

#define LOG2_THETA_OVER_HALF 0.20762050593046128f   // log2(10000)/64
#define SM_SCALE 0.08838834764831845f               // 1/sqrt(128)

__device__ __forceinline__ uint32_t h2_as_u32(__half2 h) {
    return *reinterpret_cast<uint32_t*>(&h);
}

__device__ __forceinline__ void mma_f16(float c[4],
                                        uint32_t a0, uint32_t a1, uint32_t a2, uint32_t a3,
                                        uint32_t b0, uint32_t b1) {
    asm volatile(
        "mma.sync.aligned.m16n8k16.row.col.f32.f16.f16.f32 "
        "{%0,%1,%2,%3}, {%4,%5,%6,%7}, {%8,%9}, {%0,%1,%2,%3};\n"
        : "+f"(c[0]), "+f"(c[1]), "+f"(c[2]), "+f"(c[3])
        : "r"(a0), "r"(a1), "r"(a2), "r"(a3), "r"(b0), "r"(b1));
}

__device__ __forceinline__ void cp_async16(uint32_t smem_addr, const void* gptr) {
    asm volatile("cp.async.cg.shared.global [%0], [%1], 16;\n"
                 :: "r"(smem_addr), "l"(gptr));
}
__device__ __forceinline__ void cp_async4(uint32_t smem_addr, const void* gptr) {
    asm volatile("cp.async.ca.shared.global [%0], [%1], 4;\n"
                 :: "r"(smem_addr), "l"(gptr));
}
__device__ __forceinline__ void cp_commit() {
    asm volatile("cp.async.commit_group;\n" ::: "memory");
}
template <int N>
__device__ __forceinline__ void cp_wait() {
    asm volatile("cp.async.wait_group %0;\n" :: "n"(N) : "memory");
}

// ---------------------------------------------------------------------------
// x -> fp16 elementwise
// ---------------------------------------------------------------------------
__global__ __launch_bounds__(256)
void cvt_x_kernel(const float4* __restrict__ src, __half2* __restrict__ dst, int n4) {
    int i = blockIdx.x * blockDim.x + threadIdx.x;
    if (i < n4) {
        float4 f = src[i];
        dst[2 * i]     = __floats2half2_rn(f.x, f.y);
        dst[2 * i + 1] = __floats2half2_rn(f.z, f.w);
    }
}

// All four weight transposes in ONE launch.
__global__ __launch_bounds__(256)
void cvt_w_kernel(const float* __restrict__ wq, const float* __restrict__ wk,
                  const float* __restrict__ wv, const float* __restrict__ wo) {
    __shared__ float tile[32][33];
    int id = blockIdx.x;
    const float* src; __half* dst; int N, n0, k0;
    if (id < 4096)      { src = wq; dst = g_wqh; N = 2048; int j = id;        n0 = (j & 63) * 32; k0 = (j >> 6) * 32; }
    else if (id < 5120) { src = wk; dst = g_wkh; N = 512;  int j = id - 4096; n0 = (j & 15) * 32; k0 = (j >> 4) * 32; }
    else if (id < 6144) { src = wv; dst = g_wvh; N = 512;  int j = id - 5120; n0 = (j & 15) * 32; k0 = (j >> 4) * 32; }
    else                { src = wo; dst = g_woh; N = 2048; int j = id - 6144; n0 = (j & 63) * 32; k0 = (j >> 6) * 32; }
    const int K = 2048;
    const int tx = threadIdx.x & 31;
    const int ty = threadIdx.x >> 5;   // 0..7
    #pragma unroll
    for (int r = 0; r < 32; r += 8)
        tile[r + ty][tx] = src[(size_t)(k0 + r + ty) * N + n0 + tx];
    __syncthreads();
    #pragma unroll
    for (int r = 0; r < 32; r += 8)
        dst[(size_t)(n0 + r + ty) * K + k0 + tx] = __float2half_rn(tile[tx][r + ty]);
}

// ---------------------------------------------------------------------------
// fp16 mma.sync GEMM core: 256 threads (8 warps), warp tile 64x32, BK=64.
// Word pitch 36 (== 4 mod 32, conflict-free). 3-stage cp.async, one sync/iter.
// STAGE=true: dump fp32 acc into smem staging [128][129] (caller converts).
// STAGE=false: write fp32 C directly.
// ---------------------------------------------------------------------------
#define GP   36
#define GASZ (128 * GP)
#define GSTG (2 * GASZ)
#define NSTG 3
#define GEMM_SMEM_BYTES (NSTG * GSTG * 4)   // 110592 B (staging 66048 B fits inside)
#define EPI_PITCH 129

__device__ __forceinline__ void gemm_fill(const __half* __restrict__ A,
                                          const __half* __restrict__ Bt,
                                          int K, int k0,
                                          uint32_t aAddr, uint32_t bAddr, int tid) {
    #pragma unroll
    for (int v = 0; v < 4; v++) {
        int task = tid + 256 * v;     // 1024 chunks per operand
        int r  = task >> 3;
        int ch = task & 7;
        cp_async16(aAddr + (r * GP + ch * 4) * 4, A  + (size_t)r * K + k0 + ch * 8);
        cp_async16(bAddr + (r * GP + ch * 4) * 4, Bt + (size_t)r * K + k0 + ch * 8);
    }
}

template <bool STAGE>
__device__ __forceinline__ void gemm_core(
    const __half* __restrict__ A,    // [128+][K] K-major (row block applied)
    const __half* __restrict__ Bt,   // [128+][K] K-major (col block applied)
    float* __restrict__ C, int N, int K,
    uint32_t smem_base, float* stage)
{
    const int tid  = threadIdx.x;
    const int wid  = tid >> 5;
    const int lane = tid & 31;
    const int g    = lane >> 2;
    const int tig  = lane & 3;

    const int warp_m = (wid & 1) * 64;
    const int warp_n = (wid >> 1) * 32;

    uint32_t* sm = (uint32_t*)__cvta_shared_to_generic(smem_base);

    float acc[4][4][4];
    #pragma unroll
    for (int i = 0; i < 4; i++)
        #pragma unroll
        for (int j = 0; j < 4; j++)
            #pragma unroll
            for (int c = 0; c < 4; c++) acc[i][j][c] = 0.0f;

    const int niter = K >> 6;   // BK = 64

    #pragma unroll
    for (int p = 0; p < NSTG - 1; p++) {
        uint32_t ab = smem_base + (p * GSTG) * 4;
        gemm_fill(A, Bt, K, p << 6, ab, ab + GASZ * 4, tid);
        cp_commit();
    }

    for (int i = 0; i < niter; i++) {
        cp_wait<NSTG - 2>();
        __syncthreads();

        const int ft = i + NSTG - 1;
        if (ft < niter) {
            const int fs = ft % NSTG;
            uint32_t ab = smem_base + (fs * GSTG) * 4;
            gemm_fill(A, Bt, K, ft << 6, ab, ab + GASZ * 4, tid);
        }
        cp_commit();

        const int cur = i % NSTG;
        const uint32_t* As = sm + cur * GSTG;
        const uint32_t* Bs = As + GASZ;

        #pragma unroll
        for (int ks = 0; ks < 4; ks++) {
            const int kk = ks * 8;
            uint32_t af[4][4];
            #pragma unroll
            for (int mt = 0; mt < 4; mt++) {
                int ar = warp_m + mt * 16 + g;
                af[mt][0] = As[ar * GP + kk + tig];
                af[mt][1] = As[(ar + 8) * GP + kk + tig];
                af[mt][2] = As[ar * GP + kk + tig + 4];
                af[mt][3] = As[(ar + 8) * GP + kk + tig + 4];
            }
            uint32_t bf[4][2];
            #pragma unroll
            for (int nt = 0; nt < 4; nt++) {
                int br = warp_n + nt * 8 + g;
                bf[nt][0] = Bs[br * GP + kk + tig];
                bf[nt][1] = Bs[br * GP + kk + tig + 4];
            }
            #pragma unroll
            for (int mt = 0; mt < 4; mt++)
                #pragma unroll
                for (int nt = 0; nt < 4; nt++)
                    mma_f16(acc[mt][nt], af[mt][0], af[mt][1], af[mt][2], af[mt][3],
                            bf[nt][0], bf[nt][1]);
        }
    }

    if (STAGE) {
        __syncthreads();   // all warps done reading pipeline stages
        #pragma unroll
        for (int mt = 0; mt < 4; mt++) {
            #pragma unroll
            for (int nt = 0; nt < 4; nt++) {
                int row = warp_m + mt * 16 + g;
                int col = warp_n + nt * 8 + 2 * tig;
                stage[row * EPI_PITCH + col]           = acc[mt][nt][0];
                stage[row * EPI_PITCH + col + 1]       = acc[mt][nt][1];
                stage[(row + 8) * EPI_PITCH + col]     = acc[mt][nt][2];
                stage[(row + 8) * EPI_PITCH + col + 1] = acc[mt][nt][3];
            }
        }
        __syncthreads();   // staging visible to all threads
    } else {
        float* Cw = C + (size_t)warp_m * N + warp_n;
        #pragma unroll
        for (int mt = 0; mt < 4; mt++) {
            #pragma unroll
            for (int nt = 0; nt < 4; nt++) {
                int row = mt * 16 + g;
                int col = nt * 8 + 2 * tig;
                *(float2*)(Cw + (size_t)row * N + col) =
                    make_float2(acc[mt][nt][0], acc[mt][nt][1]);
                *(float2*)(Cw + (size_t)(row + 8) * N + col) =
                    make_float2(acc[mt][nt][2], acc[mt][nt][3]);
            }
        }
    }
}

// Fused QKV projection + RoPE + V-transpose epilogue.
// grid.x: 0..15 q heads | 16..19 k heads | 20..23 v heads; grid.y = 32 row tiles.
__global__ __launch_bounds__(256, 2)
void qkv_gemm_kernel() {
    extern __shared__ uint32_t smraw[];
    uint32_t smem_base = (uint32_t)__cvta_generic_to_shared(smraw);
    float* stage = (float*)smraw;

    const int bx = blockIdx.x;
    const int by = blockIdx.y;
    const int tid = threadIdx.x;

    const __half* Bsel;
    if (bx < 16)      Bsel = g_wqh + (size_t)bx * 128 * DD;
    else if (bx < 20) Bsel = g_wkh + (size_t)(bx - 16) * 128 * DD;
    else              Bsel = g_wvh + (size_t)(bx - 20) * 128 * DD;

    gemm_core<true>(g_xh + (size_t)by * 128 * DD, Bsel,
                    nullptr, 0, DD, smem_base, stage);

    if (bx < 20) {
        // ---- rope epilogue: pairs (d, d+64) within the tile ----
        const bool isq = (bx < 16);
        const int  h   = isq ? bx : (bx - 16);
        const float sc = isq ? SM_SCALE : 1.0f;
        __half* dst = isq ? g_qh : g_kh;
        const int hstride = isq ? 2048 : 512;
        #pragma unroll
        for (int p = 0; p < 32; p++) {
            int idx = 256 * p + tid;           // 8192 pairs
            int tl  = idx >> 6;
            int d   = idx & 63;
            float x1 = stage[tl * EPI_PITCH + d];
            float x2 = stage[tl * EPI_PITCH + d + 64];
            int bt = by * 128 + tl;
            int t  = bt & (TT - 1);
            float inv = exp2f(-(float)d * LOG2_THETA_OVER_HALF);
            float ang = (float)t * inv;
            float s, c;
            sincosf(ang, &s, &c);
            __half* o = dst + (size_t)bt * hstride + h * HDIM;
            o[d]      = __float2half_rn((x1 * c - x2 * s) * sc);
            o[d + 64] = __float2half_rn((x2 * c + x1 * s) * sc);
        }
    } else {
        // ---- v epilogue: transposed fp16 write to g_vt[bkv][d][t] ----
        const int kv = bx - 20;
        #pragma unroll
        for (int p = 0; p < 64; p++) {
            int idx = 256 * p + tid;           // 16384 elements
            int tl  = idx & 127;               // consecutive lanes -> consecutive t
            int d   = idx >> 7;
            float v = stage[tl * EPI_PITCH + d];
            int bt = by * 128 + tl;
            int b  = bt >> 11;
            int t  = bt & (TT - 1);
            g_vt[((size_t)(b * NKV + kv) * HDIM + d) * TT + t] = __float2half_rn(v);
        }
    }
}

__global__ __launch_bounds__(256, 2)
void wo_gemm_kernel(float* __restrict__ C) {
    extern __shared__ uint32_t smraw[];
    uint32_t smem_base = (uint32_t)__cvta_generic_to_shared(smraw);
    gemm_core<false>(g_oh + (size_t)blockIdx.y * 128 * DD,
                     g_woh + (size_t)blockIdx.x * 128 * DD,
                     C + (size_t)blockIdx.y * 128 * DD + blockIdx.x * 128,
                     DD, DD, smem_base, nullptr);
}

// ---------------------------------------------------------------------------
// fp16 flash attention, BM=128, BN=64, HD=128, 8 warps (16 rows each).
// K/V/mask double-buffered, prefetch at top of iteration, ONE sync per iter.
// Q fragments hoisted to registers; P entirely in registers.
// smem words: Qs 8704 | Ks 2x4352=8704 | Vt 2x4608=9216 | mask 2x64=128
//   -> 26752 words = 107008 B
// ---------------------------------------------------------------------------
#define QKP 68
#define VTP 36
#define QS_OFF   0
#define KS_OFF   8704
#define VS_OFF   17408
#define MASK_OFF 26624
#define ATTN_SMEM_BYTES (26752 * 4)

__global__ __launch_bounds__(256, 1)
void attn_mma_kernel(const int* __restrict__ mask, const int* __restrict__ causal_p) {
    extern __shared__ uint32_t sm[];
    const uint32_t smem_base = (uint32_t)__cvta_generic_to_shared(sm);
    uint32_t* Qs    = sm + QS_OFF;
    int*      maskS = (int*)(sm + MASK_OFF);

    const int tid  = threadIdx.x;
    const int wid  = tid >> 5;
    const int lane = tid & 31;
    const int g    = lane >> 2;
    const int tig  = lane & 3;

    const int qb  = (gridDim.x - 1) - blockIdx.x;   // LPT
    const int h   = blockIdx.y;
    const int b   = blockIdx.z;
    const int kvh = h >> 2;
    const int causal = causal_p[0];

    const __half* qbase = g_qh + ((size_t)b * TT + qb * 128) * 2048 + h * HDIM;
    const __half* kbase = g_kh + (size_t)b * TT * 512 + kvh * HDIM;
    const __half* vtbase = g_vt + (size_t)(b * NKV + kvh) * HDIM * TT;
    const int*   mbase = mask + b * TT;

    // ---- prologue: Q whole, K0/Vt0/mask0 into buf0 ----
    #pragma unroll
    for (int it = 0; it < 8; it++) {
        int task = tid + 256 * it;            // 2048 chunks
        int r = task >> 4;
        int c = task & 15;
        cp_async16(smem_base + (QS_OFF + r * QKP + c * 4) * 4,
                   qbase + (size_t)r * 2048 + c * 8);
    }
    #pragma unroll
    for (int it = 0; it < 4; it++) {
        int task = tid + 256 * it;            // 1024 chunks
        int r = task >> 4;
        int c = task & 15;
        cp_async16(smem_base + (KS_OFF + r * QKP + c * 4) * 4,
                   kbase + (size_t)r * 512 + c * 8);
    }
    #pragma unroll
    for (int it = 0; it < 4; it++) {
        int task = tid + 256 * it;            // 1024 chunks (128 rows x 8)
        int r = task >> 3;
        int c = task & 7;
        cp_async16(smem_base + (VS_OFF + r * VTP + c * 4) * 4,
                   vtbase + (size_t)r * TT + c * 8);
    }
    if (tid < 64)
        cp_async4(smem_base + (MASK_OFF + tid) * 4, mbase + tid);
    cp_commit();

    const int r0  = 16 * wid + g;
    const int r1  = r0 + 8;
    const int qg0 = qb * 128 + r0;
    const int qg1 = qb * 128 + r1;

    float accO[16][4];
    #pragma unroll
    for (int nt = 0; nt < 16; nt++)
        #pragma unroll
        for (int c = 0; c < 4; c++) accO[nt][c] = 0.0f;

    float m0 = -1e30f, m1 = -1e30f, l0 = 0.0f, l1 = 0.0f;

    uint32_t qa[8][4];   // hoisted Q fragments (loaded at kb=0)

    const int kbmax = causal ? (2 * qb + 1) : (TT / 64 - 1);

    for (int kb = 0; kb <= kbmax; kb++) {
        const int kr0 = kb * 64;
        const int cbuf = kb & 1;

        cp_wait<0>();          // buf cbuf (K,V,mask; +Q on kb=0) resident
        __syncthreads();       // all warps past iteration kb-1 (frees nbuf)

        if (kb == 0) {
            #pragma unroll
            for (int ks = 0; ks < 8; ks++) {
                const uint32_t* qr = &Qs[r0 * QKP + ks * 8 + tig];
                qa[ks][0] = qr[0];
                qa[ks][2] = qr[4];
                qa[ks][1] = qr[8 * QKP];
                qa[ks][3] = qr[8 * QKP + 4];
            }
        }

        // ---- prefetch kb+1 into alternate buffers (full iter to land) ----
        if (kb < kbmax) {
            const int nr0 = kr0 + 64;
            const int nbuf = (kb + 1) & 1;
            #pragma unroll
            for (int it = 0; it < 4; it++) {
                int task = tid + 256 * it;
                int r = task >> 4;
                int c = task & 15;
                cp_async16(smem_base + (KS_OFF + nbuf * 4352 + r * QKP + c * 4) * 4,
                           kbase + (size_t)(nr0 + r) * 512 + c * 8);
            }
            #pragma unroll
            for (int it = 0; it < 4; it++) {
                int task = tid + 256 * it;
                int r = task >> 3;
                int c = task & 7;
                cp_async16(smem_base + (VS_OFF + nbuf * 4608 + r * VTP + c * 4) * 4,
                           vtbase + (size_t)r * TT + nr0 + c * 8);
            }
            if (tid < 64)
                cp_async4(smem_base + (MASK_OFF + nbuf * 64 + tid) * 4,
                          mbase + nr0 + tid);
        }
        cp_commit();

        // ---- S = Q @ K^T : warp computes 16 x 64, k over 8 chunks of 16 ----
        const uint32_t* Kc = sm + KS_OFF + cbuf * 4352;
        float sacc[8][4];
        #pragma unroll
        for (int nt = 0; nt < 8; nt++)
            #pragma unroll
            for (int c = 0; c < 4; c++) sacc[nt][c] = 0.0f;

        #pragma unroll
        for (int ks = 0; ks < 8; ks++) {
            #pragma unroll
            for (int nt = 0; nt < 8; nt++) {
                const uint32_t* kr = &Kc[(8 * nt + g) * QKP + ks * 8 + tig];
                mma_f16(sacc[nt], qa[ks][0], qa[ks][1], qa[ks][2], qa[ks][3],
                        kr[0], kr[4]);
            }
        }

        // ---- mask + warp-local row max ----
        const int* mcur = maskS + cbuf * 64;
        float lm0 = -1e30f, lm1 = -1e30f;
        #pragma unroll
        for (int nt = 0; nt < 8; nt++) {
            #pragma unroll
            for (int e = 0; e < 2; e++) {
                int c  = 8 * nt + 2 * tig + e;
                int kg = kr0 + c;
                bool mz = (mcur[c] == 0);
                if (mz || (causal && kg > qg0)) sacc[nt][e]     = -1e30f;
                if (mz || (causal && kg > qg1)) sacc[nt][e + 2] = -1e30f;
                lm0 = fmaxf(lm0, sacc[nt][e]);
                lm1 = fmaxf(lm1, sacc[nt][e + 2]);
            }
        }
        lm0 = fmaxf(lm0, __shfl_xor_sync(0xffffffffu, lm0, 1));
        lm0 = fmaxf(lm0, __shfl_xor_sync(0xffffffffu, lm0, 2));
        lm1 = fmaxf(lm1, __shfl_xor_sync(0xffffffffu, lm1, 1));
        lm1 = fmaxf(lm1, __shfl_xor_sync(0xffffffffu, lm1, 2));

        float mn0 = fmaxf(m0, lm0);
        float mn1 = fmaxf(m1, lm1);
        float esc0 = __expf(m0 - mn0);
        float esc1 = __expf(m1 - mn1);

        // ---- p = exp(s - m), row sums, fragments stay in registers ----
        float ls0 = 0.0f, ls1 = 0.0f;
        uint32_t pw0[8], pw1[8];
        #pragma unroll
        for (int nt = 0; nt < 8; nt++) {
            float p0 = __expf(sacc[nt][0] - mn0);
            float p1 = __expf(sacc[nt][1] - mn0);
            float p2 = __expf(sacc[nt][2] - mn1);
            float p3 = __expf(sacc[nt][3] - mn1);
            ls0 += p0 + p1;
            ls1 += p2 + p3;
            pw0[nt] = h2_as_u32(__floats2half2_rn(p0, p1));
            pw1[nt] = h2_as_u32(__floats2half2_rn(p2, p3));
        }
        ls0 += __shfl_xor_sync(0xffffffffu, ls0, 1);
        ls0 += __shfl_xor_sync(0xffffffffu, ls0, 2);
        ls1 += __shfl_xor_sync(0xffffffffu, ls1, 1);
        ls1 += __shfl_xor_sync(0xffffffffu, ls1, 2);

        l0 = l0 * esc0 + ls0;
        l1 = l1 * esc1 + ls1;
        m0 = mn0;
        m1 = mn1;

        #pragma unroll
        for (int nt = 0; nt < 16; nt++) {
            accO[nt][0] *= esc0; accO[nt][1] *= esc0;
            accO[nt][2] *= esc1; accO[nt][3] *= esc1;
        }

        // ---- O += P @ V : k = 64 keys over 4 chunks of 16 (P from regs) ----
        const uint32_t* Vc = sm + VS_OFF + cbuf * 4608;
        #pragma unroll
        for (int ks = 0; ks < 4; ks++) {
            uint32_t a0 = pw0[2 * ks];
            uint32_t a1 = pw1[2 * ks];
            uint32_t a2 = pw0[2 * ks + 1];
            uint32_t a3 = pw1[2 * ks + 1];
            #pragma unroll
            for (int nt = 0; nt < 16; nt++) {
                const uint32_t* vr = &Vc[(8 * nt + g) * VTP + ks * 8 + tig];
                mma_f16(accO[nt], a0, a1, a2, a3, vr[0], vr[4]);
            }
        }
    }

    // ---- epilogue: normalize, write fp16 ----
    float invl0 = 1.0f / l0;
    float invl1 = 1.0f / l1;
    __half2* oh0 = (__half2*)(g_oh + ((size_t)b * TT + qb * 128 + r0) * 2048 + h * HDIM);
    __half2* oh1 = (__half2*)(g_oh + ((size_t)b * TT + qb * 128 + r1) * 2048 + h * HDIM);
    #pragma unroll
    for (int nt = 0; nt < 16; nt++) {
        oh0[4 * nt + tig] = __floats2half2_rn(accO[nt][0] * invl0, accO[nt][1] * invl0);
        oh1[4 * nt + tig] = __floats2half2_rn(accO[nt][2] * invl1, accO[nt][3] * invl1);
    }
}

// ---------------------------------------------------------------------------
extern "C" void kernel_launch(void* const* d_in, const int* in_sizes, int n_in,
                              void* d_out, int out_size) {
    const float* x      = (const float*)d_in[0];
    const int*   mask   = (const int*)d_in[1];
    const int*   causal = (const int*)d_in[2];
    const float* wq     = (const float*)d_in[3];
    const float* wk     = (const float*)d_in[4];
    const float* wv     = (const float*)d_in[5];
    const float* wo     = (const float*)d_in[6];
    float* out = (float*)d_out;

    __half* xh;
    cudaGetSymbolAddress((void**)&xh, g_xh);

    const int M = BB * TT;  // 4096

    cudaFuncSetAttribute(qkv_gemm_kernel, cudaFuncAttributeMaxDynamicSharedMemorySize,
                         GEMM_SMEM_BYTES);
    cudaFuncSetAttribute(wo_gemm_kernel, cudaFuncAttributeMaxDynamicSharedMemorySize,
                         GEMM_SMEM_BYTES);
    cudaFuncSetAttribute(attn_mma_kernel, cudaFuncAttributeMaxDynamicSharedMemorySize,
                         ATTN_SMEM_BYTES);

    // x -> fp16; weights -> transposed fp16 (one launch)
    {
        int n4 = (M * DD) / 4;
        cvt_x_kernel<<<(n4 + 255) / 256, 256>>>((const float4*)x, (__half2*)xh, n4);
        cvt_w_kernel<<<10240, 256>>>(wq, wk, wv, wo);
    }

    // Fused QKV projection + RoPE + V-transpose epilogue
    qkv_gemm_kernel<<<dim3(24, M / 128), 256, GEMM_SMEM_BYTES>>>();

    // Attention (fp16 mma, register-resident P, hoisted Q)
    attn_mma_kernel<<<dim3(TT / 128, NH, BB), 256, ATTN_SMEM_BYTES>>>(mask, causal);

    // Output projection (fp16 in, fp32 out)
    wo_gemm_kernel<<<dim3(DD / 128, M / 128), 256, GEMM_SMEM_BYTES>>>(out);
}

// round 17
// speedup vs baseline: 2.3189x; 1.0397x over previous
#include <cuda_runtime.h>
#include <cuda_fp16.h>
#include <math.h>
#include <stdint.h>

#define BB   2
#define TT   2048
#define DD   2048
#define NH   16
#define NKV  4
#define HDIM 128

// fp16 operands
__device__ __half g_xh [BB*TT*DD];          // x fp16 [M][K]
__device__ __half g_wqh[NH*HDIM*DD];        // weights transposed [N][K]
__device__ __half g_wkh[NKV*HDIM*DD];
__device__ __half g_wvh[NKV*HDIM*DD];
__device__ __half g_woh[DD*DD];
__device__ __half g_qh [BB*TT*NH*HDIM];     // rope'd q (scaled) fp16
__device__ __half g_kh [BB*TT*NKV*HDIM];    // rope'd k fp16
__device__ __half g_vt [BB*NKV*HDIM*TT];    // v transposed [bkv][hd][t] fp16
__device__ __half g_oh [BB*TT*NH*HDIM];     // attention out fp16

#define LOG2_THETA_OVER_HALF 0.20762050593046128f   // log2(10000)/64
#define SM_SCALE 0.08838834764831845f               // 1/sqrt(128)

__device__ __forceinline__ uint32_t h2_as_u32(__half2 h) {
    return *reinterpret_cast<uint32_t*>(&h);
}

__device__ __forceinline__ void mma_f16(float c[4],
                                        uint32_t a0, uint32_t a1, uint32_t a2, uint32_t a3,
                                        uint32_t b0, uint32_t b1) {
    asm volatile(
        "mma.sync.aligned.m16n8k16.row.col.f32.f16.f16.f32 "
        "{%0,%1,%2,%3}, {%4,%5,%6,%7}, {%8,%9}, {%0,%1,%2,%3};\n"
        : "+f"(c[0]), "+f"(c[1]), "+f"(c[2]), "+f"(c[3])
        : "r"(a0), "r"(a1), "r"(a2), "r"(a3), "r"(b0), "r"(b1));
}

__device__ __forceinline__ void cp_async16(uint32_t smem_addr, const void* gptr) {
    asm volatile("cp.async.cg.shared.global [%0], [%1], 16;\n"
                 :: "r"(smem_addr), "l"(gptr));
}
__device__ __forceinline__ void cp_async4(uint32_t smem_addr, const void* gptr) {
    asm volatile("cp.async.ca.shared.global [%0], [%1], 4;\n"
                 :: "r"(smem_addr), "l"(gptr));
}
__device__ __forceinline__ void cp_commit() {
    asm volatile("cp.async.commit_group;\n" ::: "memory");
}
template <int N>
__device__ __forceinline__ void cp_wait() {
    asm volatile("cp.async.wait_group %0;\n" :: "n"(N) : "memory");
}

// ---------------------------------------------------------------------------
// x -> fp16 elementwise
// ---------------------------------------------------------------------------
__global__ __launch_bounds__(256)
void cvt_x_kernel(const float4* __restrict__ src, __half2* __restrict__ dst, int n4) {
    int i = blockIdx.x * blockDim.x + threadIdx.x;
    if (i < n4) {
        float4 f = src[i];
        dst[2 * i]     = __floats2half2_rn(f.x, f.y);
        dst[2 * i + 1] = __floats2half2_rn(f.z, f.w);
    }
}

// All four weight transposes in ONE launch.
__global__ __launch_bounds__(256)
void cvt_w_kernel(const float* __restrict__ wq, const float* __restrict__ wk,
                  const float* __restrict__ wv, const float* __restrict__ wo) {
    __shared__ float tile[32][33];
    int id = blockIdx.x;
    const float* src; __half* dst; int N, n0, k0;
    if (id < 4096)      { src = wq; dst = g_wqh; N = 2048; int j = id;        n0 = (j & 63) * 32; k0 = (j >> 6) * 32; }
    else if (id < 5120) { src = wk; dst = g_wkh; N = 512;  int j = id - 4096; n0 = (j & 15) * 32; k0 = (j >> 4) * 32; }
    else if (id < 6144) { src = wv; dst = g_wvh; N = 512;  int j = id - 5120; n0 = (j & 15) * 32; k0 = (j >> 4) * 32; }
    else                { src = wo; dst = g_woh; N = 2048; int j = id - 6144; n0 = (j & 63) * 32; k0 = (j >> 6) * 32; }
    const int K = 2048;
    const int tx = threadIdx.x & 31;
    const int ty = threadIdx.x >> 5;   // 0..7
    #pragma unroll
    for (int r = 0; r < 32; r += 8)
        tile[r + ty][tx] = src[(size_t)(k0 + r + ty) * N + n0 + tx];
    __syncthreads();
    #pragma unroll
    for (int r = 0; r < 32; r += 8)
        dst[(size_t)(n0 + r + ty) * K + k0 + tx] = __float2half_rn(tile[tx][r + ty]);
}

// ---------------------------------------------------------------------------
// fp16 mma.sync GEMM core: 256 threads (8 warps), warp tile 64x32, BK=64.
// Word pitch 36 (== 4 mod 32, conflict-free). 3-stage cp.async, one sync/iter.
// ---------------------------------------------------------------------------
#define GP   36
#define GASZ (128 * GP)
#define GSTG (2 * GASZ)
#define NSTG 3
#define GEMM_SMEM_BYTES (NSTG * GSTG * 4)   // 110592 B
#define EPI_PITCH 129

__device__ __forceinline__ void gemm_fill(const __half* __restrict__ A,
                                          const __half* __restrict__ Bt,
                                          int K, int k0,
                                          uint32_t aAddr, uint32_t bAddr, int tid) {
    #pragma unroll
    for (int v = 0; v < 4; v++) {
        int task = tid + 256 * v;     // 1024 chunks per operand
        int r  = task >> 3;
        int ch = task & 7;
        cp_async16(aAddr + (r * GP + ch * 4) * 4, A  + (size_t)r * K + k0 + ch * 8);
        cp_async16(bAddr + (r * GP + ch * 4) * 4, Bt + (size_t)r * K + k0 + ch * 8);
    }
}

template <bool STAGE>
__device__ __forceinline__ void gemm_core(
    const __half* __restrict__ A, const __half* __restrict__ Bt,
    float* __restrict__ C, int N, int K,
    uint32_t smem_base, float* stage)
{
    const int tid  = threadIdx.x;
    const int wid  = tid >> 5;
    const int lane = tid & 31;
    const int g    = lane >> 2;
    const int tig  = lane & 3;

    const int warp_m = (wid & 1) * 64;
    const int warp_n = (wid >> 1) * 32;

    uint32_t* sm = (uint32_t*)__cvta_shared_to_generic(smem_base);

    float acc[4][4][4];
    #pragma unroll
    for (int i = 0; i < 4; i++)
        #pragma unroll
        for (int j = 0; j < 4; j++)
            #pragma unroll
            for (int c = 0; c < 4; c++) acc[i][j][c] = 0.0f;

    const int niter = K >> 6;   // BK = 64

    #pragma unroll
    for (int p = 0; p < NSTG - 1; p++) {
        uint32_t ab = smem_base + (p * GSTG) * 4;
        gemm_fill(A, Bt, K, p << 6, ab, ab + GASZ * 4, tid);
        cp_commit();
    }

    for (int i = 0; i < niter; i++) {
        cp_wait<NSTG - 2>();
        __syncthreads();

        const int ft = i + NSTG - 1;
        if (ft < niter) {
            const int fs = ft % NSTG;
            uint32_t ab = smem_base + (fs * GSTG) * 4;
            gemm_fill(A, Bt, K, ft << 6, ab, ab + GASZ * 4, tid);
        }
        cp_commit();

        const int cur = i % NSTG;
        const uint32_t* As = sm + cur * GSTG;
        const uint32_t* Bs = As + GASZ;

        #pragma unroll
        for (int ks = 0; ks < 4; ks++) {
            const int kk = ks * 8;
            uint32_t af[4][4];
            #pragma unroll
            for (int mt = 0; mt < 4; mt++) {
                int ar = warp_m + mt * 16 + g;
                af[mt][0] = As[ar * GP + kk + tig];
                af[mt][1] = As[(ar + 8) * GP + kk + tig];
                af[mt][2] = As[ar * GP + kk + tig + 4];
                af[mt][3] = As[(ar + 8) * GP + kk + tig + 4];
            }
            uint32_t bf[4][2];
            #pragma unroll
            for (int nt = 0; nt < 4; nt++) {
                int br = warp_n + nt * 8 + g;
                bf[nt][0] = Bs[br * GP + kk + tig];
                bf[nt][1] = Bs[br * GP + kk + tig + 4];
            }
            #pragma unroll
            for (int mt = 0; mt < 4; mt++)
                #pragma unroll
                for (int nt = 0; nt < 4; nt++)
                    mma_f16(acc[mt][nt], af[mt][0], af[mt][1], af[mt][2], af[mt][3],
                            bf[nt][0], bf[nt][1]);
        }
    }

    if (STAGE) {
        __syncthreads();
        #pragma unroll
        for (int mt = 0; mt < 4; mt++) {
            #pragma unroll
            for (int nt = 0; nt < 4; nt++) {
                int row = warp_m + mt * 16 + g;
                int col = warp_n + nt * 8 + 2 * tig;
                stage[row * EPI_PITCH + col]           = acc[mt][nt][0];
                stage[row * EPI_PITCH + col + 1]       = acc[mt][nt][1];
                stage[(row + 8) * EPI_PITCH + col]     = acc[mt][nt][2];
                stage[(row + 8) * EPI_PITCH + col + 1] = acc[mt][nt][3];
            }
        }
        __syncthreads();
    } else {
        float* Cw = C + (size_t)warp_m * N + warp_n;
        #pragma unroll
        for (int mt = 0; mt < 4; mt++) {
            #pragma unroll
            for (int nt = 0; nt < 4; nt++) {
                int row = mt * 16 + g;
                int col = nt * 8 + 2 * tig;
                *(float2*)(Cw + (size_t)row * N + col) =
                    make_float2(acc[mt][nt][0], acc[mt][nt][1]);
                *(float2*)(Cw + (size_t)(row + 8) * N + col) =
                    make_float2(acc[mt][nt][2], acc[mt][nt][3]);
            }
        }
    }
}

// Fused QKV projection + RoPE + V-transpose epilogue.
__global__ __launch_bounds__(256, 2)
void qkv_gemm_kernel() {
    extern __shared__ uint32_t smraw[];
    uint32_t smem_base = (uint32_t)__cvta_generic_to_shared(smraw);
    float* stage = (float*)smraw;

    const int bx = blockIdx.x;
    const int by = blockIdx.y;
    const int tid = threadIdx.x;

    const __half* Bsel;
    if (bx < 16)      Bsel = g_wqh + (size_t)bx * 128 * DD;
    else if (bx < 20) Bsel = g_wkh + (size_t)(bx - 16) * 128 * DD;
    else              Bsel = g_wvh + (size_t)(bx - 20) * 128 * DD;

    gemm_core<true>(g_xh + (size_t)by * 128 * DD, Bsel,
                    nullptr, 0, DD, smem_base, stage);

    if (bx < 20) {
        const bool isq = (bx < 16);
        const int  h   = isq ? bx : (bx - 16);
        const float sc = isq ? SM_SCALE : 1.0f;
        __half* dst = isq ? g_qh : g_kh;
        const int hstride = isq ? 2048 : 512;
        #pragma unroll
        for (int p = 0; p < 32; p++) {
            int idx = 256 * p + tid;
            int tl  = idx >> 6;
            int d   = idx & 63;
            float x1 = stage[tl * EPI_PITCH + d];
            float x2 = stage[tl * EPI_PITCH + d + 64];
            int bt = by * 128 + tl;
            int t  = bt & (TT - 1);
            float inv = exp2f(-(float)d * LOG2_THETA_OVER_HALF);
            float ang = (float)t * inv;
            float s, c;
            sincosf(ang, &s, &c);
            __half* o = dst + (size_t)bt * hstride + h * HDIM;
            o[d]      = __float2half_rn((x1 * c - x2 * s) * sc);
            o[d + 64] = __float2half_rn((x2 * c + x1 * s) * sc);
        }
    } else {
        const int kv = bx - 20;
        #pragma unroll
        for (int p = 0; p < 64; p++) {
            int idx = 256 * p + tid;
            int tl  = idx & 127;
            int d   = idx >> 7;
            float v = stage[tl * EPI_PITCH + d];
            int bt = by * 128 + tl;
            int b  = bt >> 11;
            int t  = bt & (TT - 1);
            g_vt[((size_t)(b * NKV + kv) * HDIM + d) * TT + t] = __float2half_rn(v);
        }
    }
}

__global__ __launch_bounds__(256, 2)
void wo_gemm_kernel(float* __restrict__ C) {
    extern __shared__ uint32_t smraw[];
    uint32_t smem_base = (uint32_t)__cvta_generic_to_shared(smraw);
    gemm_core<false>(g_oh + (size_t)blockIdx.y * 128 * DD,
                     g_woh + (size_t)blockIdx.x * 128 * DD,
                     C + (size_t)blockIdx.y * 128 * DD + blockIdx.x * 128,
                     DD, DD, smem_base, nullptr);
}

// ---------------------------------------------------------------------------
// fp16 flash attention, BM=64, BN=64, HD=128, 4 warps (16 rows each),
// 128 threads -> 2 CTAs/SM co-resident (independent barrier domains).
// K/V/mask double-buffered, prefetch at top of iteration, ONE sync per iter.
// Q fragments hoisted to registers; P entirely in registers.
// smem words: Qs 64*68=4352 | Ks 2x4352=8704 | Vt 2x4608=9216 | mask 2x64=128
//   -> 22400 words = 89600 B
// ---------------------------------------------------------------------------
#define QKP 68
#define VTP 36
#define QS_OFF   0
#define KS_OFF   4352
#define VS_OFF   13056
#define MASK_OFF 22272
#define ATTN_SMEM_BYTES (22400 * 4)
#define ATHR 128

__global__ __launch_bounds__(ATHR, 2)
void attn_mma_kernel(const int* __restrict__ mask, const int* __restrict__ causal_p) {
    extern __shared__ uint32_t sm[];
    const uint32_t smem_base = (uint32_t)__cvta_generic_to_shared(sm);
    uint32_t* Qs    = sm + QS_OFF;
    int*      maskS = (int*)(sm + MASK_OFF);

    const int tid  = threadIdx.x;
    const int wid  = tid >> 5;        // 0..3
    const int lane = tid & 31;
    const int g    = lane >> 2;
    const int tig  = lane & 3;

    const int qb  = (gridDim.x - 1) - blockIdx.x;   // LPT (64-row blocks)
    const int h   = blockIdx.y;
    const int b   = blockIdx.z;
    const int kvh = h >> 2;
    const int causal = causal_p[0];

    const __half* qbase = g_qh + ((size_t)b * TT + qb * 64) * 2048 + h * HDIM;
    const __half* kbase = g_kh + (size_t)b * TT * 512 + kvh * HDIM;
    const __half* vtbase = g_vt + (size_t)(b * NKV + kvh) * HDIM * TT;
    const int*   mbase = mask + b * TT;

    // ---- prologue: Q whole (64 rows), K0/Vt0/mask0 into buf0 ----
    #pragma unroll
    for (int it = 0; it < 8; it++) {
        int task = tid + ATHR * it;           // 1024 chunks
        int r = task >> 4;
        int c = task & 15;
        cp_async16(smem_base + (QS_OFF + r * QKP + c * 4) * 4,
                   qbase + (size_t)r * 2048 + c * 8);
    }
    #pragma unroll
    for (int it = 0; it < 8; it++) {
        int task = tid + ATHR * it;           // 1024 chunks
        int r = task >> 4;
        int c = task & 15;
        cp_async16(smem_base + (KS_OFF + r * QKP + c * 4) * 4,
                   kbase + (size_t)r * 512 + c * 8);
    }
    #pragma unroll
    for (int it = 0; it < 8; it++) {
        int task = tid + ATHR * it;           // 1024 chunks (128 rows x 8)
        int r = task >> 3;
        int c = task & 7;
        cp_async16(smem_base + (VS_OFF + r * VTP + c * 4) * 4,
                   vtbase + (size_t)r * TT + c * 8);
    }
    if (tid < 64)
        cp_async4(smem_base + (MASK_OFF + tid) * 4, mbase + tid);
    cp_commit();

    const int r0  = 16 * wid + g;
    const int r1  = r0 + 8;
    const int qg0 = qb * 64 + r0;
    const int qg1 = qb * 64 + r1;

    float accO[16][4];
    #pragma unroll
    for (int nt = 0; nt < 16; nt++)
        #pragma unroll
        for (int c = 0; c < 4; c++) accO[nt][c] = 0.0f;

    float m0 = -1e30f, m1 = -1e30f, l0 = 0.0f, l1 = 0.0f;

    uint32_t qa[8][4];   // hoisted Q fragments (loaded at kb=0)

    const int kbmax = causal ? qb : (TT / 64 - 1);

    for (int kb = 0; kb <= kbmax; kb++) {
        const int kr0 = kb * 64;
        const int cbuf = kb & 1;

        cp_wait<0>();          // buf cbuf (K,V,mask; +Q on kb=0) resident
        __syncthreads();       // all warps past iteration kb-1 (frees nbuf)

        if (kb == 0) {
            #pragma unroll
            for (int ks = 0; ks < 8; ks++) {
                const uint32_t* qr = &Qs[r0 * QKP + ks * 8 + tig];
                qa[ks][0] = qr[0];
                qa[ks][2] = qr[4];
                qa[ks][1] = qr[8 * QKP];
                qa[ks][3] = qr[8 * QKP + 4];
            }
        }

        // ---- prefetch kb+1 into alternate buffers (full iter to land) ----
        if (kb < kbmax) {
            const int nr0 = kr0 + 64;
            const int nbuf = (kb + 1) & 1;
            #pragma unroll
            for (int it = 0; it < 8; it++) {
                int task = tid + ATHR * it;
                int r = task >> 4;
                int c = task & 15;
                cp_async16(smem_base + (KS_OFF + nbuf * 4352 + r * QKP + c * 4) * 4,
                           kbase + (size_t)(nr0 + r) * 512 + c * 8);
            }
            #pragma unroll
            for (int it = 0; it < 8; it++) {
                int task = tid + ATHR * it;
                int r = task >> 3;
                int c = task & 7;
                cp_async16(smem_base + (VS_OFF + nbuf * 4608 + r * VTP + c * 4) * 4,
                           vtbase + (size_t)r * TT + nr0 + c * 8);
            }
            if (tid < 64)
                cp_async4(smem_base + (MASK_OFF + nbuf * 64 + tid) * 4,
                          mbase + nr0 + tid);
        }
        cp_commit();

        // ---- S = Q @ K^T : warp computes 16 x 64, k over 8 chunks of 16 ----
        const uint32_t* Kc = sm + KS_OFF + cbuf * 4352;
        float sacc[8][4];
        #pragma unroll
        for (int nt = 0; nt < 8; nt++)
            #pragma unroll
            for (int c = 0; c < 4; c++) sacc[nt][c] = 0.0f;

        #pragma unroll
        for (int ks = 0; ks < 8; ks++) {
            #pragma unroll
            for (int nt = 0; nt < 8; nt++) {
                const uint32_t* kr = &Kc[(8 * nt + g) * QKP + ks * 8 + tig];
                mma_f16(sacc[nt], qa[ks][0], qa[ks][1], qa[ks][2], qa[ks][3],
                        kr[0], kr[4]);
            }
        }

        // ---- mask + warp-local row max ----
        const int* mcur = maskS + cbuf * 64;
        float lm0 = -1e30f, lm1 = -1e30f;
        #pragma unroll
        for (int nt = 0; nt < 8; nt++) {
            #pragma unroll
            for (int e = 0; e < 2; e++) {
                int c  = 8 * nt + 2 * tig + e;
                int kg = kr0 + c;
                bool mz = (mcur[c] == 0);
                if (mz || (causal && kg > qg0)) sacc[nt][e]     = -1e30f;
                if (mz || (causal && kg > qg1)) sacc[nt][e + 2] = -1e30f;
                lm0 = fmaxf(lm0, sacc[nt][e]);
                lm1 = fmaxf(lm1, sacc[nt][e + 2]);
            }
        }
        lm0 = fmaxf(lm0, __shfl_xor_sync(0xffffffffu, lm0, 1));
        lm0 = fmaxf(lm0, __shfl_xor_sync(0xffffffffu, lm0, 2));
        lm1 = fmaxf(lm1, __shfl_xor_sync(0xffffffffu, lm1, 1));
        lm1 = fmaxf(lm1, __shfl_xor_sync(0xffffffffu, lm1, 2));

        float mn0 = fmaxf(m0, lm0);
        float mn1 = fmaxf(m1, lm1);
        float esc0 = __expf(m0 - mn0);
        float esc1 = __expf(m1 - mn1);

        // ---- p = exp(s - m), row sums, fragments stay in registers ----
        float ls0 = 0.0f, ls1 = 0.0f;
        uint32_t pw0[8], pw1[8];
        #pragma unroll
        for (int nt = 0; nt < 8; nt++) {
            float p0 = __expf(sacc[nt][0] - mn0);
            float p1 = __expf(sacc[nt][1] - mn0);
            float p2 = __expf(sacc[nt][2] - mn1);
            float p3 = __expf(sacc[nt][3] - mn1);
            ls0 += p0 + p1;
            ls1 += p2 + p3;
            pw0[nt] = h2_as_u32(__floats2half2_rn(p0, p1));
            pw1[nt] = h2_as_u32(__floats2half2_rn(p2, p3));
        }
        ls0 += __shfl_xor_sync(0xffffffffu, ls0, 1);
        ls0 += __shfl_xor_sync(0xffffffffu, ls0, 2);
        ls1 += __shfl_xor_sync(0xffffffffu, ls1, 1);
        ls1 += __shfl_xor_sync(0xffffffffu, ls1, 2);

        l0 = l0 * esc0 + ls0;
        l1 = l1 * esc1 + ls1;
        m0 = mn0;
        m1 = mn1;

        #pragma unroll
        for (int nt = 0; nt < 16; nt++) {
            accO[nt][0] *= esc0; accO[nt][1] *= esc0;
            accO[nt][2] *= esc1; accO[nt][3] *= esc1;
        }

        // ---- O += P @ V : k = 64 keys over 4 chunks of 16 (P from regs) ----
        const uint32_t* Vc = sm + VS_OFF + cbuf * 4608;
        #pragma unroll
        for (int ks = 0; ks < 4; ks++) {
            uint32_t a0 = pw0[2 * ks];
            uint32_t a1 = pw1[2 * ks];
            uint32_t a2 = pw0[2 * ks + 1];
            uint32_t a3 = pw1[2 * ks + 1];
            #pragma unroll
            for (int nt = 0; nt < 16; nt++) {
                const uint32_t* vr = &Vc[(8 * nt + g) * VTP + ks * 8 + tig];
                mma_f16(accO[nt], a0, a1, a2, a3, vr[0], vr[4]);
            }
        }
    }

    // ---- epilogue: normalize, write fp16 ----
    float invl0 = 1.0f / l0;
    float invl1 = 1.0f / l1;
    __half2* oh0 = (__half2*)(g_oh + ((size_t)b * TT + qb * 64 + r0) * 2048 + h * HDIM);
    __half2* oh1 = (__half2*)(g_oh + ((size_t)b * TT + qb * 64 + r1) * 2048 + h * HDIM);
    #pragma unroll
    for (int nt = 0; nt < 16; nt++) {
        oh0[4 * nt + tig] = __floats2half2_rn(accO[nt][0] * invl0, accO[nt][1] * invl0);
        oh1[4 * nt + tig] = __floats2half2_rn(accO[nt][2] * invl1, accO[nt][3] * invl1);
    }
}

// ---------------------------------------------------------------------------
extern "C" void kernel_launch(void* const* d_in, const int* in_sizes, int n_in,
                              void* d_out, int out_size) {
    const float* x      = (const float*)d_in[0];
    const int*   mask   = (const int*)d_in[1];
    const int*   causal = (const int*)d_in[2];
    const float* wq     = (const float*)d_in[3];
    const float* wk     = (const float*)d_in[4];
    const float* wv     = (const float*)d_in[5];
    const float* wo     = (const float*)d_in[6];
    float* out = (float*)d_out;

    __half* xh;
    cudaGetSymbolAddress((void**)&xh, g_xh);

    const int M = BB * TT;  // 4096

    cudaFuncSetAttribute(qkv_gemm_kernel, cudaFuncAttributeMaxDynamicSharedMemorySize,
                         GEMM_SMEM_BYTES);
    cudaFuncSetAttribute(wo_gemm_kernel, cudaFuncAttributeMaxDynamicSharedMemorySize,
                         GEMM_SMEM_BYTES);
    cudaFuncSetAttribute(attn_mma_kernel, cudaFuncAttributeMaxDynamicSharedMemorySize,
                         ATTN_SMEM_BYTES);

    // x -> fp16; weights -> transposed fp16 (one launch)
    {
        int n4 = (M * DD) / 4;
        cvt_x_kernel<<<(n4 + 255) / 256, 256>>>((const float4*)x, (__half2*)xh, n4);
        cvt_w_kernel<<<10240, 256>>>(wq, wk, wv, wo);
    }

    // Fused QKV projection + RoPE + V-transpose epilogue
    qkv_gemm_kernel<<<dim3(24, M / 128), 256, GEMM_SMEM_BYTES>>>();

    // Attention (fp16 mma, BM=64, 2 CTAs/SM)
    attn_mma_kernel<<<dim3(TT / 64, NH, BB), ATHR, ATTN_SMEM_BYTES>>>(mask, causal);

    // Output projection (fp16 in, fp32 out)
    wo_gemm_kernel<<<dim3(DD / 128, M / 128), 256, GEMM_SMEM_BYTES>>>(out);
}